// round 12
// baseline (speedup 1.0000x reference)
#include <cuda_runtime.h>
#include <cuda_bf16.h>
#include <cuda_fp16.h>

#define C_DIM 256
#define N_PIX 4096
#define B_DIM 2
#define RED 64
#define NH 4
#define HD 16
#define SPLIT 4
#define KEYS_PER_SPLIT (N_PIX / SPLIT)   // 1024
#define QSCALE_LOG2E 0.36067376022224085f

// ---------------- scratch (static device globals) ----------------------------
__device__ float g_dyn[B_DIM * N_PIX];
// partials: [s][b][n][r] with r = h*16+d  (contiguous 64-float row per query)
__device__ float g_pacc[SPLIT * B_DIM * N_PIX * RED];
__device__ float g_pl[SPLIT * B_DIM * NH * N_PIX];
__device__ __nv_bfloat16 g_qh[B_DIM * NH * N_PIX * HD];   // [bh][n][d], pre-scaled
__device__ __nv_bfloat16 g_kh[B_DIM * NH * N_PIX * HD];   // [bh][n][d]
__device__ __half        g_vth[B_DIM * NH * HD * N_PIX];  // [bh][d][n], f16
// precomputed weights: rows 0-191 = qkv_w * nw (hi/lo), rows 192-319 = conv1_w
__device__ __nv_bfloat16 g_wh[320 * C_DIM];
__device__ __nv_bfloat16 g_wl[320 * C_DIM];
__device__ float g_W1[192];
__device__ float g_WB[192];

// ---------------- helpers -----------------------------------------------------
__device__ __forceinline__ unsigned pkhf(float hi, float lo) {
    unsigned d;
    asm("cvt.rn.f16x2.f32 %0, %1, %2;" : "=r"(d) : "f"(hi), "f"(lo));
    return d;
}
__device__ __forceinline__ unsigned hmin2(unsigned a, unsigned b) {
    unsigned d;
    asm("min.f16x2 %0, %1, %2;" : "=r"(d) : "r"(a), "r"(b));
    return d;
}
__device__ __forceinline__ unsigned hex2(unsigned a) {
    unsigned d;
    asm("ex2.approx.f16x2 %0, %1;" : "=r"(d) : "r"(a));
    return d;
}
__device__ __forceinline__ unsigned hadd2u(unsigned a, unsigned b) {
    unsigned d;
    asm("add.f16x2 %0, %1, %2;" : "=r"(d) : "r"(a), "r"(b));
    return d;
}
__device__ __forceinline__ void mma16816(float* d, const unsigned* a,
                                         unsigned b0, unsigned b1) {
    asm volatile(
        "mma.sync.aligned.m16n8k16.row.col.f32.bf16.bf16.f32 "
        "{%0,%1,%2,%3}, {%4,%5,%6,%7}, {%8,%9}, {%0,%1,%2,%3};"
        : "+f"(d[0]), "+f"(d[1]), "+f"(d[2]), "+f"(d[3])
        : "r"(a[0]), "r"(a[1]), "r"(a[2]), "r"(a[3]), "r"(b0), "r"(b1));
}
__device__ __forceinline__ void mma16816h(float* d, const unsigned* a,
                                          unsigned b0, unsigned b1) {
    asm volatile(
        "mma.sync.aligned.m16n8k16.row.col.f32.f16.f16.f32 "
        "{%0,%1,%2,%3}, {%4,%5,%6,%7}, {%8,%9}, {%0,%1,%2,%3};"
        : "+f"(d[0]), "+f"(d[1]), "+f"(d[2]), "+f"(d[3])
        : "r"(a[0]), "r"(a[1]), "r"(a[2]), "r"(a[3]), "r"(b0), "r"(b1));
}

// ---------------- 0) weight prep ---------------------------------------------
__global__ void wprep_kernel(const float* __restrict__ qkvw,
                             const float* __restrict__ c1w,
                             const float* __restrict__ nw,
                             const float* __restrict__ nb) {
    int o = blockIdx.x;          // 0..319
    int c = threadIdx.x;         // 0..255
    __shared__ float r1[8], r2[8];
    float s1 = 0.f, s2 = 0.f;
    if (o < 192) {
        float w = qkvw[o * C_DIM + c];
        float wp = w * nw[c];
        __nv_bfloat16 hi = __float2bfloat16(wp);
        g_wh[o * C_DIM + c] = hi;
        g_wl[o * C_DIM + c] = __float2bfloat16(wp - __bfloat162float(hi));
        s1 = wp;
        s2 = w * nb[c];
    } else {
        float w = c1w[(o - 192) * C_DIM + c];
        __nv_bfloat16 hi = __float2bfloat16(w);
        g_wh[o * C_DIM + c] = hi;
        g_wl[o * C_DIM + c] = __float2bfloat16(w - __bfloat162float(hi));
    }
    if (o < 192) {
#pragma unroll
        for (int m = 16; m; m >>= 1) {
            s1 += __shfl_xor_sync(0xffffffffu, s1, m);
            s2 += __shfl_xor_sync(0xffffffffu, s2, m);
        }
        int wp_ = c >> 5;
        if ((c & 31) == 0) { r1[wp_] = s1; r2[wp_] = s2; }
        __syncthreads();
        if (c == 0) {
            float a = 0.f, bsum = 0.f;
#pragma unroll
            for (int i = 0; i < 8; i++) { a += r1[i]; bsum += r2[i]; }
            g_W1[o] = a;
            g_WB[o] = bsum;
        }
    }
}

// ---------------- 1) fused pre kernel: LN + QKV + dyn via MMA ----------------
#define XROW 264
#define WROW 72

__global__ __launch_bounds__(256, 1) void pre_kernel(const float* __restrict__ x,
                                                     const float* __restrict__ b1,
                                                     const float* __restrict__ w2,
                                                     const float* __restrict__ b2) {
    extern __shared__ __align__(16) char smem[];
    __nv_bfloat16* XH = (__nv_bfloat16*)smem;                  // [64][XROW]
    __nv_bfloat16* XL = XH + 64 * XROW;
    __nv_bfloat16* WHs = XL + 64 * XROW;                       // [320][WROW]
    __nv_bfloat16* WLs = WHs + 320 * WROW;
    float* PS = (float*)(WLs + 320 * WROW);                    // [8][64]
    float* MU = PS + 512;
    float* RS = MU + 64;
    float* DR = RS + 64;

    int t = threadIdx.x;
    int gp0 = blockIdx.x * 64;
    int b = gp0 >> 12, n0 = gp0 & 4095;

    {
        int px = t & 63, grp = t >> 6;
        const float* xb = x + (size_t)(b * C_DIM) * N_PIX + n0 + px;
        float sum = 0.f, sq = 0.f;
#pragma unroll
        for (int i = 0; i < 64; i++) {
            int c = i * 4 + grp;
            float v = xb[(size_t)c * N_PIX];
            sum += v;
            sq += v * v;
            __nv_bfloat16 hi = __float2bfloat16(v);
            XH[px * XROW + c] = hi;
            XL[px * XROW + c] = __float2bfloat16(v - __bfloat162float(hi));
        }
        PS[grp * 64 + px] = sum;
        PS[256 + grp * 64 + px] = sq;
        if (t < 64) DR[t] = 0.f;
    }
    __syncthreads();
    if (t < 64) {
        float a = PS[t] + PS[64 + t] + PS[128 + t] + PS[192 + t];
        float q = PS[256 + t] + PS[320 + t] + PS[384 + t] + PS[448 + t];
        float m = a * (1.f / 256.f);
        float var = q * (1.f / 256.f) - m * m;
        MU[t] = m;
        RS[t] = rsqrtf(var + 1e-5f);
    }

    int warp = t >> 5, lane = t & 31;
    int g = lane >> 2, tg = lane & 3;
    int mg = warp & 3, ng = warp >> 2;
    int px0 = ng * 32;

    float acc[5][4][4];
#pragma unroll
    for (int mi = 0; mi < 5; mi++)
#pragma unroll
        for (int nt = 0; nt < 4; nt++)
#pragma unroll
            for (int f = 0; f < 4; f++) acc[mi][nt][f] = 0.f;

    for (int kc = 0; kc < C_DIM; kc += 64) {
        __syncthreads();
#pragma unroll
        for (int r = 0; r < 10; r++) {
            int e = t + 256 * r;
            int o = e >> 3, kk = e & 7;
            *(uint4*)&WHs[o * WROW + kk * 8] = *(const uint4*)&g_wh[o * C_DIM + kc + kk * 8];
            *(uint4*)&WLs[o * WROW + kk * 8] = *(const uint4*)&g_wl[o * C_DIM + kc + kk * 8];
        }
        __syncthreads();
#pragma unroll
        for (int ks = 0; ks < 4; ks++) {
            int kl = ks * 16 + 2 * tg;
            unsigned bh0[4], bh1[4], bl0[4], bl1[4];
#pragma unroll
            for (int nt = 0; nt < 4; nt++) {
                int xr = (px0 + nt * 8 + g) * XROW + kc + kl;
                bh0[nt] = *(const unsigned*)&XH[xr];
                bh1[nt] = *(const unsigned*)&XH[xr + 8];
                bl0[nt] = *(const unsigned*)&XL[xr];
                bl1[nt] = *(const unsigned*)&XL[xr + 8];
            }
#pragma unroll
            for (int mi = 0; mi < 5; mi++) {
                int o0 = (mg * 5 + mi) * 16;
                unsigned ah[4], al[4];
                ah[0] = *(const unsigned*)&WHs[(o0 + g) * WROW + kl];
                ah[1] = *(const unsigned*)&WHs[(o0 + g + 8) * WROW + kl];
                ah[2] = *(const unsigned*)&WHs[(o0 + g) * WROW + kl + 8];
                ah[3] = *(const unsigned*)&WHs[(o0 + g + 8) * WROW + kl + 8];
                al[0] = *(const unsigned*)&WLs[(o0 + g) * WROW + kl];
                al[1] = *(const unsigned*)&WLs[(o0 + g + 8) * WROW + kl];
                al[2] = *(const unsigned*)&WLs[(o0 + g) * WROW + kl + 8];
                al[3] = *(const unsigned*)&WLs[(o0 + g + 8) * WROW + kl + 8];
#pragma unroll
                for (int nt = 0; nt < 4; nt++) {
                    mma16816(acc[mi][nt], ah, bh0[nt], bh1[nt]);
                    mma16816(acc[mi][nt], ah, bl0[nt], bl1[nt]);
                    mma16816(acc[mi][nt], al, bh0[nt], bh1[nt]);
                }
            }
        }
    }

    // ---- epilogue ----
#pragma unroll
    for (int mi = 0; mi < 5; mi++) {
        int m = mg * 5 + mi;
        if (m >= 12) continue;
#pragma unroll
        for (int nt = 0; nt < 4; nt++) {
            int pxa = px0 + nt * 8 + 2 * tg;
#pragma unroll
            for (int rr = 0; rr < 2; rr++) {
                int o = m * 16 + g + rr * 8;
                float W1v = g_W1[o], WBv = g_WB[o];
                float v0 = RS[pxa] * (acc[mi][nt][rr * 2] - MU[pxa] * W1v) + WBv;
                float v1 = RS[pxa + 1] * (acc[mi][nt][rr * 2 + 1] - MU[pxa + 1] * W1v) + WBv;
                int n = n0 + pxa;
                if (o < 64) {
                    int h = o >> 4, d = o & 15;
                    size_t idx = ((size_t)(b * NH + h) * N_PIX + n) * HD + d;
                    g_qh[idx] = __float2bfloat16(v0 * QSCALE_LOG2E);
                    g_qh[idx + HD] = __float2bfloat16(v1 * QSCALE_LOG2E);
                } else if (o < 128) {
                    int oo = o - 64, h = oo >> 4, d = oo & 15;
                    size_t idx = ((size_t)(b * NH + h) * N_PIX + n) * HD + d;
                    g_kh[idx] = __float2bfloat16(v0);
                    g_kh[idx + HD] = __float2bfloat16(v1);
                } else {
                    int oo = o - 128, h = oo >> 4, d = oo & 15;
                    size_t idx = (size_t)(b * NH + h) * HD * N_PIX + (size_t)d * N_PIX + n;
                    *(unsigned*)&g_vth[idx] = pkhf(v1, v0);
                }
            }
        }
    }
    // --- dyn reduction (conv tiles live in warps mg>=2, m>=12) ---
    if (mg >= 2) {
#pragma unroll
        for (int nt = 0; nt < 4; nt++) {
            float d0 = 0.f, d1 = 0.f;
#pragma unroll
            for (int mi = 0; mi < 5; mi++) {
                int m = mg * 5 + mi;
                if (m < 12) continue;
#pragma unroll
                for (int rr = 0; rr < 2; rr++) {
                    int co = (m - 12) * 16 + g + rr * 8;
                    float bb = b1[co], ww = w2[co];
                    d0 += ww * fmaxf(acc[mi][nt][rr * 2] + bb, 0.f);
                    d1 += ww * fmaxf(acc[mi][nt][rr * 2 + 1] + bb, 0.f);
                }
            }
#pragma unroll
            for (int mk = 4; mk <= 16; mk <<= 1) {
                d0 += __shfl_xor_sync(0xffffffffu, d0, mk);
                d1 += __shfl_xor_sync(0xffffffffu, d1, mk);
            }
            if (g == 0) {
                int pxa = px0 + nt * 8 + 2 * tg;
                atomicAdd(&DR[pxa], d0);
                atomicAdd(&DR[pxa + 1], d1);
            }
        }
    }
    __syncthreads();
    if (t < 64) g_dyn[gp0 + t] = DR[t] + b2[0];
}

// ---------------- 2) tensor-core flash attention (f16x2 softmax) -------------
#define KS_STRIDE 24
#define VT_STRIDE 136
#define S_CLAMP2 0x4B004B00u   // f16x2 {14.0, 14.0}: exp2 overflow guard

__global__ void attn_kernel() {
    __shared__ __align__(16) __nv_bfloat16 Kh_s[128 * KS_STRIDE];
    __shared__ __align__(16) __half Vh_s[HD * VT_STRIDE];

    int tid = threadIdx.x;
    int warp = tid >> 5, lane = tid & 31;
    int g = lane >> 2, tg = lane & 3;
    int bh = blockIdx.y;
    int split = blockIdx.z;
    int qbase = blockIdx.x * 64 + warp * 16;

    const __nv_bfloat16* qb = g_qh + ((size_t)bh * N_PIX + qbase) * HD;
    unsigned aqh[4];
    aqh[0] = *(const unsigned*)(qb + g * HD + 2 * tg);
    aqh[1] = *(const unsigned*)(qb + (g + 8) * HD + 2 * tg);
    aqh[2] = *(const unsigned*)(qb + g * HD + 2 * tg + 8);
    aqh[3] = *(const unsigned*)(qb + (g + 8) * HD + 2 * tg + 8);

    float o0[4] = {0.f, 0.f, 0.f, 0.f};
    float o1[4] = {0.f, 0.f, 0.f, 0.f};
    float l_r = 0.f, l_r8 = 0.f;

    int kstart = split * KEYS_PER_SPLIT;
    const __nv_bfloat16* kh_g = g_kh + (size_t)bh * N_PIX * HD;
    const __half* vh_g = g_vth + (size_t)bh * HD * N_PIX;

    for (int st = 0; st < KEYS_PER_SPLIT / 128; st++) {
        int k0 = kstart + st * 128;
        __syncthreads();
        {
            int key = tid >> 1, seg = tid & 1;
#pragma unroll
            for (int r = 0; r < 2; r++) {
                *(uint4*)&Kh_s[(key + 64 * r) * KS_STRIDE + seg * 8] =
                    *(const uint4*)(kh_g + ((size_t)(k0 + key + 64 * r)) * HD + seg * 8);
            }
            int d = tid >> 4, s8 = tid & 15;
#pragma unroll
            for (int r = 0; r < 2; r++) {
                *(uint4*)&Vh_s[(d + 8 * r) * VT_STRIDE + s8 * 8] =
                    *(const uint4*)(vh_g + (size_t)(d + 8 * r) * N_PIX + k0 + s8 * 8);
            }
        }
        __syncthreads();

#pragma unroll
        for (int c16 = 0; c16 < 128; c16 += 16) {
            float s0[4] = {0.f, 0.f, 0.f, 0.f};
            float s1[4] = {0.f, 0.f, 0.f, 0.f};
            {
                int kb = (c16 + g) * KS_STRIDE + 2 * tg;
                mma16816(s0, aqh, *(const unsigned*)&Kh_s[kb],
                                  *(const unsigned*)&Kh_s[kb + 8]);
            }
            {
                int kb = (c16 + 8 + g) * KS_STRIDE + 2 * tg;
                mma16816(s1, aqh, *(const unsigned*)&Kh_s[kb],
                                  *(const unsigned*)&Kh_s[kb + 8]);
            }
            unsigned pa[4];
            pa[0] = hex2(hmin2(pkhf(s0[1], s0[0]), S_CLAMP2));
            pa[1] = hex2(hmin2(pkhf(s0[3], s0[2]), S_CLAMP2));
            pa[2] = hex2(hmin2(pkhf(s1[1], s1[0]), S_CLAMP2));
            pa[3] = hex2(hmin2(pkhf(s1[3], s1[2]), S_CLAMP2));
            {
                unsigned u0 = hadd2u(pa[0], pa[2]);
                unsigned u1 = hadd2u(pa[1], pa[3]);
                float2 f0 = __half22float2(*(const __half2*)&u0);
                float2 f1 = __half22float2(*(const __half2*)&u1);
                l_r  += f0.x + f0.y;
                l_r8 += f1.x + f1.y;
            }
            {
                int vb = g * VT_STRIDE + c16 + 2 * tg;
                mma16816h(o0, pa, *(const unsigned*)&Vh_s[vb],
                                  *(const unsigned*)&Vh_s[vb + 8]);
            }
            {
                int vb = (8 + g) * VT_STRIDE + c16 + 2 * tg;
                mma16816h(o1, pa, *(const unsigned*)&Vh_s[vb],
                                  *(const unsigned*)&Vh_s[vb + 8]);
            }
        }
    }
    l_r  += __shfl_xor_sync(0xffffffffu, l_r, 1);
    l_r  += __shfl_xor_sync(0xffffffffu, l_r, 2);
    l_r8 += __shfl_xor_sync(0xffffffffu, l_r8, 1);
    l_r8 += __shfl_xor_sync(0xffffffffu, l_r8, 2);

    // partials layout: [s][b][n][r], r = h*16 + d  -> coalesced combine reads
    int h = bh & 3, bb = bh >> 2;
    int row0 = qbase + g, row8 = qbase + g + 8;
    size_t base0 = ((size_t)(split * B_DIM + bb) * N_PIX + row0) * RED + h * HD;
    size_t base8 = ((size_t)(split * B_DIM + bb) * N_PIX + row8) * RED + h * HD;
    *(float2*)(g_pacc + base0 + 2 * tg)     = make_float2(o0[0], o0[1]);
    *(float2*)(g_pacc + base0 + 8 + 2 * tg) = make_float2(o1[0], o1[1]);
    *(float2*)(g_pacc + base8 + 2 * tg)     = make_float2(o0[2], o0[3]);
    *(float2*)(g_pacc + base8 + 8 + 2 * tg) = make_float2(o1[2], o1[3]);
    size_t pb = (size_t)(split * B_DIM * NH + bh) * N_PIX;
    if (tg == 0) {
        g_pl[pb + row0] = l_r;
        g_pl[pb + row8] = l_r8;
    }
}

// ---------------- 3) out projection (fused combine, k-major smem) ------------
// grid 128: block = 64 px x ALL 256 channels. A staged once; Bs re-staged per
// 64-channel chunk (w is L2-resident). Smem tiles k-major -> float4 LDS.
__global__ __launch_bounds__(256) void out_kernel(const float* __restrict__ w,
                                                  const float* __restrict__ x,
                                                  const float* __restrict__ gamma,
                                                  float* __restrict__ out) {
    __shared__ float As[RED][68];    // [r][px]
    __shared__ float Bs[RED][68];    // [r][c]
    __shared__ float LI[64][4];      // dyn/l per (px, head)
    int tid = threadIdx.x;           // 256
    int tx = tid & 15, ty = tid >> 4;
    int n0 = blockIdx.x * 64;
    int b = n0 >> 12, nb0 = n0 & 4095;

    // LI: thread -> px = tid>>2, h = tid&3
    {
        int px = tid >> 2, hh = tid & 3;
        int n = nb0 + px;
        int bh = b * NH + hh;
        float l = 0.f;
#pragma unroll
        for (int s = 0; s < SPLIT; s++)
            l += g_pl[((size_t)s * B_DIM * NH + bh) * N_PIX + n];
        LI[px][hh] = g_dyn[b * N_PIX + n] / l;
    }
    __syncthreads();
    // stage A (combine SPLIT partials, coalesced rows): e -> r = e&63, px = e>>6
#pragma unroll
    for (int it = 0; it < 16; it++) {
        int e = tid + 256 * it;
        int r = e & 63, px = e >> 6;
        int n = nb0 + px;
        size_t base = ((size_t)b * N_PIX + n) * RED + r;
        float a = 0.f;
#pragma unroll
        for (int s = 0; s < SPLIT; s++)
            a += g_pacc[(size_t)s * (B_DIM * N_PIX * RED) + base];
        As[r][px] = a * LI[px][r >> 4];
    }

    float gm = gamma[0];
    for (int cc = 0; cc < 4; cc++) {
        __syncthreads();             // prev compute done (and A ready on cc=0)
        // stage B chunk: e -> r = e&63, c = e>>6 (coalesced w rows)
#pragma unroll
        for (int it = 0; it < 16; it++) {
            int e = tid + 256 * it;
            int r = e & 63, c = e >> 6;
            Bs[r][c] = w[(cc * 64 + c) * RED + r];
        }
        __syncthreads();
        float acc[4][4] = {};
#pragma unroll
        for (int k = 0; k < RED; k++) {
            float4 a4 = *(const float4*)&As[k][ty * 4];
            float4 b4 = *(const float4*)&Bs[k][tx * 4];
            float av[4] = {a4.x, a4.y, a4.z, a4.w};
            float bv[4] = {b4.x, b4.y, b4.z, b4.w};
#pragma unroll
            for (int i = 0; i < 4; i++)
#pragma unroll
                for (int j = 0; j < 4; j++) acc[i][j] += av[i] * bv[j];
        }
        int n = nb0 + ty * 4;
#pragma unroll
        for (int j = 0; j < 4; j++) {
            int c = cc * 64 + tx * 4 + j;
            size_t base = ((size_t)(b * C_DIM + c)) * N_PIX + n;
            float4 xv = *(const float4*)(x + base);
            float4 r;
            r.x = 1.f / (1.f + __expf(-(gm * acc[0][j] + xv.x)));
            r.y = 1.f / (1.f + __expf(-(gm * acc[1][j] + xv.y)));
            r.z = 1.f / (1.f + __expf(-(gm * acc[2][j] + xv.z)));
            r.w = 1.f / (1.f + __expf(-(gm * acc[3][j] + xv.w)));
            *(float4*)(out + base) = r;
        }
    }
}

// ---------------- launch ------------------------------------------------------
extern "C" void kernel_launch(void* const* d_in, const int* in_sizes, int n_in,
                              void* d_out, int out_size) {
    const float* x     = (const float*)d_in[0];
    const float* nw    = (const float*)d_in[1];
    const float* nb    = (const float*)d_in[2];
    const float* qkvw  = (const float*)d_in[3];
    const float* outw  = (const float*)d_in[4];
    const float* c1w   = (const float*)d_in[5];
    const float* c1b   = (const float*)d_in[6];
    const float* c2w   = (const float*)d_in[7];
    const float* c2b   = (const float*)d_in[8];
    const float* gamma = (const float*)d_in[9];
    float* out = (float*)d_out;

    int smem_bytes = (64 * XROW * 2 + 320 * WROW * 2) * 2 + (512 + 64 + 64 + 64) * 4;
    cudaFuncSetAttribute(pre_kernel, cudaFuncAttributeMaxDynamicSharedMemorySize,
                         smem_bytes);

    wprep_kernel<<<320, 256>>>(qkvw, c1w, nw, nb);
    pre_kernel<<<128, 256, smem_bytes>>>(x, c1b, c2w, c2b);
    attn_kernel<<<dim3(N_PIX / 64, B_DIM * NH, SPLIT), 128>>>();
    out_kernel<<<(B_DIM * N_PIX) / 64, 256>>>(outw, x, gamma, out);
}

// round 13
// speedup vs baseline: 1.0340x; 1.0340x over previous
#include <cuda_runtime.h>
#include <cuda_bf16.h>
#include <cuda_fp16.h>

#define C_DIM 256
#define N_PIX 4096
#define B_DIM 2
#define RED 64
#define NH 4
#define HD 16
#define SPLIT 4
#define KEYS_PER_SPLIT (N_PIX / SPLIT)   // 1024
#define QSCALE_LOG2E 0.36067376022224085f

// ---------------- scratch (static device globals) ----------------------------
__device__ float g_dyn[B_DIM * N_PIX];
// partials: [s][b][n][r] with r = h*16+d  (contiguous 64-float row per query)
__device__ float g_pacc[SPLIT * B_DIM * N_PIX * RED];
__device__ float g_pl[SPLIT * B_DIM * NH * N_PIX];
__device__ __nv_bfloat16 g_qh[B_DIM * NH * N_PIX * HD];   // [bh][n][d], pre-scaled
__device__ __nv_bfloat16 g_kh[B_DIM * NH * N_PIX * HD];   // [bh][n][d]
__device__ __half        g_vth[B_DIM * NH * HD * N_PIX];  // [bh][d][n], f16
// precomputed weights: rows 0-191 = qkv_w * nw (hi/lo), rows 192-319 = conv1_w
__device__ __nv_bfloat16 g_wh[320 * C_DIM];
__device__ __nv_bfloat16 g_wl[320 * C_DIM];
__device__ float g_W1[192];
__device__ float g_WB[192];

// ---------------- helpers -----------------------------------------------------
__device__ __forceinline__ unsigned pkhf(float hi, float lo) {
    unsigned d;
    asm("cvt.rn.f16x2.f32 %0, %1, %2;" : "=r"(d) : "f"(hi), "f"(lo));
    return d;
}
__device__ __forceinline__ unsigned hmin2(unsigned a, unsigned b) {
    unsigned d;
    asm("min.f16x2 %0, %1, %2;" : "=r"(d) : "r"(a), "r"(b));
    return d;
}
__device__ __forceinline__ unsigned hex2(unsigned a) {
    unsigned d;
    asm("ex2.approx.f16x2 %0, %1;" : "=r"(d) : "r"(a));
    return d;
}
__device__ __forceinline__ unsigned hadd2u(unsigned a, unsigned b) {
    unsigned d;
    asm("add.f16x2 %0, %1, %2;" : "=r"(d) : "r"(a), "r"(b));
    return d;
}
__device__ __forceinline__ void mma16816(float* d, const unsigned* a,
                                         unsigned b0, unsigned b1) {
    asm volatile(
        "mma.sync.aligned.m16n8k16.row.col.f32.bf16.bf16.f32 "
        "{%0,%1,%2,%3}, {%4,%5,%6,%7}, {%8,%9}, {%0,%1,%2,%3};"
        : "+f"(d[0]), "+f"(d[1]), "+f"(d[2]), "+f"(d[3])
        : "r"(a[0]), "r"(a[1]), "r"(a[2]), "r"(a[3]), "r"(b0), "r"(b1));
}
__device__ __forceinline__ void mma16816h(float* d, const unsigned* a,
                                          unsigned b0, unsigned b1) {
    asm volatile(
        "mma.sync.aligned.m16n8k16.row.col.f32.f16.f16.f32 "
        "{%0,%1,%2,%3}, {%4,%5,%6,%7}, {%8,%9}, {%0,%1,%2,%3};"
        : "+f"(d[0]), "+f"(d[1]), "+f"(d[2]), "+f"(d[3])
        : "r"(a[0]), "r"(a[1]), "r"(a[2]), "r"(a[3]), "r"(b0), "r"(b1));
}

// ---------------- 0) weight prep ---------------------------------------------
__global__ void wprep_kernel(const float* __restrict__ qkvw,
                             const float* __restrict__ c1w,
                             const float* __restrict__ nw,
                             const float* __restrict__ nb) {
    int o = blockIdx.x;          // 0..319
    int c = threadIdx.x;         // 0..255
    __shared__ float r1[8], r2[8];
    float s1 = 0.f, s2 = 0.f;
    if (o < 192) {
        float w = qkvw[o * C_DIM + c];
        float wp = w * nw[c];
        __nv_bfloat16 hi = __float2bfloat16(wp);
        g_wh[o * C_DIM + c] = hi;
        g_wl[o * C_DIM + c] = __float2bfloat16(wp - __bfloat162float(hi));
        s1 = wp;
        s2 = w * nb[c];
    } else {
        float w = c1w[(o - 192) * C_DIM + c];
        __nv_bfloat16 hi = __float2bfloat16(w);
        g_wh[o * C_DIM + c] = hi;
        g_wl[o * C_DIM + c] = __float2bfloat16(w - __bfloat162float(hi));
    }
    if (o < 192) {
#pragma unroll
        for (int m = 16; m; m >>= 1) {
            s1 += __shfl_xor_sync(0xffffffffu, s1, m);
            s2 += __shfl_xor_sync(0xffffffffu, s2, m);
        }
        int wp_ = c >> 5;
        if ((c & 31) == 0) { r1[wp_] = s1; r2[wp_] = s2; }
        __syncthreads();
        if (c == 0) {
            float a = 0.f, bsum = 0.f;
#pragma unroll
            for (int i = 0; i < 8; i++) { a += r1[i]; bsum += r2[i]; }
            g_W1[o] = a;
            g_WB[o] = bsum;
        }
    }
}

// ---------------- 1) fused pre kernel: LN + QKV + dyn via MMA ----------------
#define XROW 264
#define WROW 72

__global__ __launch_bounds__(256, 1) void pre_kernel(const float* __restrict__ x,
                                                     const float* __restrict__ b1,
                                                     const float* __restrict__ w2,
                                                     const float* __restrict__ b2) {
    extern __shared__ __align__(16) char smem[];
    __nv_bfloat16* XH = (__nv_bfloat16*)smem;                  // [64][XROW]
    __nv_bfloat16* XL = XH + 64 * XROW;
    __nv_bfloat16* WHs = XL + 64 * XROW;                       // [320][WROW]
    __nv_bfloat16* WLs = WHs + 320 * WROW;
    float* PS = (float*)(WLs + 320 * WROW);                    // [8][64]
    float* MU = PS + 512;
    float* RS = MU + 64;
    float* DR = RS + 64;

    int t = threadIdx.x;
    int gp0 = blockIdx.x * 64;
    int b = gp0 >> 12, n0 = gp0 & 4095;

    {
        int px = t & 63, grp = t >> 6;
        const float* xb = x + (size_t)(b * C_DIM) * N_PIX + n0 + px;
        float sum = 0.f, sq = 0.f;
#pragma unroll
        for (int i = 0; i < 64; i++) {
            int c = i * 4 + grp;
            float v = xb[(size_t)c * N_PIX];
            sum += v;
            sq += v * v;
            __nv_bfloat16 hi = __float2bfloat16(v);
            XH[px * XROW + c] = hi;
            XL[px * XROW + c] = __float2bfloat16(v - __bfloat162float(hi));
        }
        PS[grp * 64 + px] = sum;
        PS[256 + grp * 64 + px] = sq;
        if (t < 64) DR[t] = 0.f;
    }
    __syncthreads();
    if (t < 64) {
        float a = PS[t] + PS[64 + t] + PS[128 + t] + PS[192 + t];
        float q = PS[256 + t] + PS[320 + t] + PS[384 + t] + PS[448 + t];
        float m = a * (1.f / 256.f);
        float var = q * (1.f / 256.f) - m * m;
        MU[t] = m;
        RS[t] = rsqrtf(var + 1e-5f);
    }

    int warp = t >> 5, lane = t & 31;
    int g = lane >> 2, tg = lane & 3;
    int mg = warp & 3, ng = warp >> 2;
    int px0 = ng * 32;

    float acc[5][4][4];
#pragma unroll
    for (int mi = 0; mi < 5; mi++)
#pragma unroll
        for (int nt = 0; nt < 4; nt++)
#pragma unroll
            for (int f = 0; f < 4; f++) acc[mi][nt][f] = 0.f;

    for (int kc = 0; kc < C_DIM; kc += 64) {
        __syncthreads();
#pragma unroll
        for (int r = 0; r < 10; r++) {
            int e = t + 256 * r;
            int o = e >> 3, kk = e & 7;
            *(uint4*)&WHs[o * WROW + kk * 8] = *(const uint4*)&g_wh[o * C_DIM + kc + kk * 8];
            *(uint4*)&WLs[o * WROW + kk * 8] = *(const uint4*)&g_wl[o * C_DIM + kc + kk * 8];
        }
        __syncthreads();
#pragma unroll
        for (int ks = 0; ks < 4; ks++) {
            int kl = ks * 16 + 2 * tg;
            unsigned bh0[4], bh1[4], bl0[4], bl1[4];
#pragma unroll
            for (int nt = 0; nt < 4; nt++) {
                int xr = (px0 + nt * 8 + g) * XROW + kc + kl;
                bh0[nt] = *(const unsigned*)&XH[xr];
                bh1[nt] = *(const unsigned*)&XH[xr + 8];
                bl0[nt] = *(const unsigned*)&XL[xr];
                bl1[nt] = *(const unsigned*)&XL[xr + 8];
            }
#pragma unroll
            for (int mi = 0; mi < 5; mi++) {
                int o0 = (mg * 5 + mi) * 16;
                unsigned ah[4], al[4];
                ah[0] = *(const unsigned*)&WHs[(o0 + g) * WROW + kl];
                ah[1] = *(const unsigned*)&WHs[(o0 + g + 8) * WROW + kl];
                ah[2] = *(const unsigned*)&WHs[(o0 + g) * WROW + kl + 8];
                ah[3] = *(const unsigned*)&WHs[(o0 + g + 8) * WROW + kl + 8];
                al[0] = *(const unsigned*)&WLs[(o0 + g) * WROW + kl];
                al[1] = *(const unsigned*)&WLs[(o0 + g + 8) * WROW + kl];
                al[2] = *(const unsigned*)&WLs[(o0 + g) * WROW + kl + 8];
                al[3] = *(const unsigned*)&WLs[(o0 + g + 8) * WROW + kl + 8];
#pragma unroll
                for (int nt = 0; nt < 4; nt++) {
                    mma16816(acc[mi][nt], ah, bh0[nt], bh1[nt]);
                    mma16816(acc[mi][nt], ah, bl0[nt], bl1[nt]);
                    mma16816(acc[mi][nt], al, bh0[nt], bh1[nt]);
                }
            }
        }
    }

    // ---- epilogue ----
#pragma unroll
    for (int mi = 0; mi < 5; mi++) {
        int m = mg * 5 + mi;
        if (m >= 12) continue;
#pragma unroll
        for (int nt = 0; nt < 4; nt++) {
            int pxa = px0 + nt * 8 + 2 * tg;
#pragma unroll
            for (int rr = 0; rr < 2; rr++) {
                int o = m * 16 + g + rr * 8;
                float W1v = g_W1[o], WBv = g_WB[o];
                float v0 = RS[pxa] * (acc[mi][nt][rr * 2] - MU[pxa] * W1v) + WBv;
                float v1 = RS[pxa + 1] * (acc[mi][nt][rr * 2 + 1] - MU[pxa + 1] * W1v) + WBv;
                int n = n0 + pxa;
                if (o < 64) {
                    int h = o >> 4, d = o & 15;
                    size_t idx = ((size_t)(b * NH + h) * N_PIX + n) * HD + d;
                    g_qh[idx] = __float2bfloat16(v0 * QSCALE_LOG2E);
                    g_qh[idx + HD] = __float2bfloat16(v1 * QSCALE_LOG2E);
                } else if (o < 128) {
                    int oo = o - 64, h = oo >> 4, d = oo & 15;
                    size_t idx = ((size_t)(b * NH + h) * N_PIX + n) * HD + d;
                    g_kh[idx] = __float2bfloat16(v0);
                    g_kh[idx + HD] = __float2bfloat16(v1);
                } else {
                    int oo = o - 128, h = oo >> 4, d = oo & 15;
                    size_t idx = (size_t)(b * NH + h) * HD * N_PIX + (size_t)d * N_PIX + n;
                    *(unsigned*)&g_vth[idx] = pkhf(v1, v0);
                }
            }
        }
    }
    // --- dyn reduction (conv tiles live in warps mg>=2, m>=12) ---
    if (mg >= 2) {
#pragma unroll
        for (int nt = 0; nt < 4; nt++) {
            float d0 = 0.f, d1 = 0.f;
#pragma unroll
            for (int mi = 0; mi < 5; mi++) {
                int m = mg * 5 + mi;
                if (m < 12) continue;
#pragma unroll
                for (int rr = 0; rr < 2; rr++) {
                    int co = (m - 12) * 16 + g + rr * 8;
                    float bb = b1[co], ww = w2[co];
                    d0 += ww * fmaxf(acc[mi][nt][rr * 2] + bb, 0.f);
                    d1 += ww * fmaxf(acc[mi][nt][rr * 2 + 1] + bb, 0.f);
                }
            }
#pragma unroll
            for (int mk = 4; mk <= 16; mk <<= 1) {
                d0 += __shfl_xor_sync(0xffffffffu, d0, mk);
                d1 += __shfl_xor_sync(0xffffffffu, d1, mk);
            }
            if (g == 0) {
                int pxa = px0 + nt * 8 + 2 * tg;
                atomicAdd(&DR[pxa], d0);
                atomicAdd(&DR[pxa + 1], d1);
            }
        }
    }
    __syncthreads();
    if (t < 64) g_dyn[gp0 + t] = DR[t] + b2[0];
}

// ---------------- 2) tensor-core flash attention (f16x2 softmax) -------------
#define KS_STRIDE 24
#define VT_STRIDE 136
#define S_CLAMP2 0x4B004B00u   // f16x2 {14.0, 14.0}: exp2 overflow guard

__global__ void attn_kernel() {
    __shared__ __align__(16) __nv_bfloat16 Kh_s[128 * KS_STRIDE];
    __shared__ __align__(16) __half Vh_s[HD * VT_STRIDE];

    int tid = threadIdx.x;
    int warp = tid >> 5, lane = tid & 31;
    int g = lane >> 2, tg = lane & 3;
    int bh = blockIdx.y;
    int split = blockIdx.z;
    int qbase = blockIdx.x * 64 + warp * 16;

    const __nv_bfloat16* qb = g_qh + ((size_t)bh * N_PIX + qbase) * HD;
    unsigned aqh[4];
    aqh[0] = *(const unsigned*)(qb + g * HD + 2 * tg);
    aqh[1] = *(const unsigned*)(qb + (g + 8) * HD + 2 * tg);
    aqh[2] = *(const unsigned*)(qb + g * HD + 2 * tg + 8);
    aqh[3] = *(const unsigned*)(qb + (g + 8) * HD + 2 * tg + 8);

    float o0[4] = {0.f, 0.f, 0.f, 0.f};
    float o1[4] = {0.f, 0.f, 0.f, 0.f};
    float l_r = 0.f, l_r8 = 0.f;

    int kstart = split * KEYS_PER_SPLIT;
    const __nv_bfloat16* kh_g = g_kh + (size_t)bh * N_PIX * HD;
    const __half* vh_g = g_vth + (size_t)bh * HD * N_PIX;

    for (int st = 0; st < KEYS_PER_SPLIT / 128; st++) {
        int k0 = kstart + st * 128;
        __syncthreads();
        {
            int key = tid >> 1, seg = tid & 1;
#pragma unroll
            for (int r = 0; r < 2; r++) {
                *(uint4*)&Kh_s[(key + 64 * r) * KS_STRIDE + seg * 8] =
                    *(const uint4*)(kh_g + ((size_t)(k0 + key + 64 * r)) * HD + seg * 8);
            }
            int d = tid >> 4, s8 = tid & 15;
#pragma unroll
            for (int r = 0; r < 2; r++) {
                *(uint4*)&Vh_s[(d + 8 * r) * VT_STRIDE + s8 * 8] =
                    *(const uint4*)(vh_g + (size_t)(d + 8 * r) * N_PIX + k0 + s8 * 8);
            }
        }
        __syncthreads();

#pragma unroll
        for (int c16 = 0; c16 < 128; c16 += 16) {
            float s0[4] = {0.f, 0.f, 0.f, 0.f};
            float s1[4] = {0.f, 0.f, 0.f, 0.f};
            {
                int kb = (c16 + g) * KS_STRIDE + 2 * tg;
                mma16816(s0, aqh, *(const unsigned*)&Kh_s[kb],
                                  *(const unsigned*)&Kh_s[kb + 8]);
            }
            {
                int kb = (c16 + 8 + g) * KS_STRIDE + 2 * tg;
                mma16816(s1, aqh, *(const unsigned*)&Kh_s[kb],
                                  *(const unsigned*)&Kh_s[kb + 8]);
            }
            unsigned pa[4];
            pa[0] = hex2(hmin2(pkhf(s0[1], s0[0]), S_CLAMP2));
            pa[1] = hex2(hmin2(pkhf(s0[3], s0[2]), S_CLAMP2));
            pa[2] = hex2(hmin2(pkhf(s1[1], s1[0]), S_CLAMP2));
            pa[3] = hex2(hmin2(pkhf(s1[3], s1[2]), S_CLAMP2));
            {
                unsigned u0 = hadd2u(pa[0], pa[2]);
                unsigned u1 = hadd2u(pa[1], pa[3]);
                float2 f0 = __half22float2(*(const __half2*)&u0);
                float2 f1 = __half22float2(*(const __half2*)&u1);
                l_r  += f0.x + f0.y;
                l_r8 += f1.x + f1.y;
            }
            {
                int vb = g * VT_STRIDE + c16 + 2 * tg;
                mma16816h(o0, pa, *(const unsigned*)&Vh_s[vb],
                                  *(const unsigned*)&Vh_s[vb + 8]);
            }
            {
                int vb = (8 + g) * VT_STRIDE + c16 + 2 * tg;
                mma16816h(o1, pa, *(const unsigned*)&Vh_s[vb],
                                  *(const unsigned*)&Vh_s[vb + 8]);
            }
        }
    }
    l_r  += __shfl_xor_sync(0xffffffffu, l_r, 1);
    l_r  += __shfl_xor_sync(0xffffffffu, l_r, 2);
    l_r8 += __shfl_xor_sync(0xffffffffu, l_r8, 1);
    l_r8 += __shfl_xor_sync(0xffffffffu, l_r8, 2);

    // partials layout: [s][b][n][r], r = h*16 + d  -> coalesced combine reads
    int h = bh & 3, bb = bh >> 2;
    int row0 = qbase + g, row8 = qbase + g + 8;
    size_t base0 = ((size_t)(split * B_DIM + bb) * N_PIX + row0) * RED + h * HD;
    size_t base8 = ((size_t)(split * B_DIM + bb) * N_PIX + row8) * RED + h * HD;
    *(float2*)(g_pacc + base0 + 2 * tg)     = make_float2(o0[0], o0[1]);
    *(float2*)(g_pacc + base0 + 8 + 2 * tg) = make_float2(o1[0], o1[1]);
    *(float2*)(g_pacc + base8 + 2 * tg)     = make_float2(o0[2], o0[3]);
    *(float2*)(g_pacc + base8 + 8 + 2 * tg) = make_float2(o1[2], o1[3]);
    size_t pb = (size_t)(split * B_DIM * NH + bh) * N_PIX;
    if (tg == 0) {
        g_pl[pb + row0] = l_r;
        g_pl[pb + row8] = l_r8;
    }
}

// ---------------- 3) out projection (fused combine, k-major smem, 512 blocks)
// grid (128, 4): x = 64-pixel tile, y = 64-channel chunk. Combines SPLIT
// partials during A staging (coalesced rows); k-major smem -> float4 LDS.
__global__ __launch_bounds__(256) void out_kernel(const float* __restrict__ w,
                                                  const float* __restrict__ x,
                                                  const float* __restrict__ gamma,
                                                  float* __restrict__ out) {
    __shared__ float As[RED][68];    // [r][px]
    __shared__ float Bs[RED][68];    // [r][c]
    __shared__ float LI[64][4];      // dyn/l per (px, head)
    int tid = threadIdx.x;           // 256
    int tx = tid & 15, ty = tid >> 4;
    int n0 = blockIdx.x * 64;
    int c0 = blockIdx.y * 64;
    int b = n0 >> 12, nb0 = n0 & 4095;

    // LI: thread -> px = tid>>2, h = tid&3
    {
        int px = tid >> 2, hh = tid & 3;
        int n = nb0 + px;
        int bh = b * NH + hh;
        float l = 0.f;
#pragma unroll
        for (int s = 0; s < SPLIT; s++)
            l += g_pl[((size_t)s * B_DIM * NH + bh) * N_PIX + n];
        LI[px][hh] = g_dyn[b * N_PIX + n] / l;
    }
    // stage B chunk: e -> r = e&63, c = e>>6 (coalesced w rows)
#pragma unroll
    for (int it = 0; it < 16; it++) {
        int e = tid + 256 * it;
        int r = e & 63, c = e >> 6;
        Bs[r][c] = w[(c0 + c) * RED + r];
    }
    __syncthreads();
    // stage A (combine SPLIT partials, coalesced rows): e -> r = e&63, px = e>>6
#pragma unroll
    for (int it = 0; it < 16; it++) {
        int e = tid + 256 * it;
        int r = e & 63, px = e >> 6;
        int n = nb0 + px;
        size_t base = ((size_t)b * N_PIX + n) * RED + r;
        float a = 0.f;
#pragma unroll
        for (int s = 0; s < SPLIT; s++)
            a += g_pacc[(size_t)s * (B_DIM * N_PIX * RED) + base];
        As[r][px] = a * LI[px][r >> 4];
    }
    __syncthreads();

    float acc[4][4] = {};
#pragma unroll
    for (int k = 0; k < RED; k++) {
        float4 a4 = *(const float4*)&As[k][ty * 4];
        float4 b4 = *(const float4*)&Bs[k][tx * 4];
        float av[4] = {a4.x, a4.y, a4.z, a4.w};
        float bv[4] = {b4.x, b4.y, b4.z, b4.w};
#pragma unroll
        for (int i = 0; i < 4; i++)
#pragma unroll
            for (int j = 0; j < 4; j++) acc[i][j] += av[i] * bv[j];
    }
    float gm = gamma[0];
    int n = nb0 + ty * 4;
#pragma unroll
    for (int j = 0; j < 4; j++) {
        int c = c0 + tx * 4 + j;
        size_t base = ((size_t)(b * C_DIM + c)) * N_PIX + n;
        float4 xv = *(const float4*)(x + base);
        float4 r;
        r.x = 1.f / (1.f + __expf(-(gm * acc[0][j] + xv.x)));
        r.y = 1.f / (1.f + __expf(-(gm * acc[1][j] + xv.y)));
        r.z = 1.f / (1.f + __expf(-(gm * acc[2][j] + xv.z)));
        r.w = 1.f / (1.f + __expf(-(gm * acc[3][j] + xv.w)));
        *(float4*)(out + base) = r;
    }
}

// ---------------- launch ------------------------------------------------------
extern "C" void kernel_launch(void* const* d_in, const int* in_sizes, int n_in,
                              void* d_out, int out_size) {
    const float* x     = (const float*)d_in[0];
    const float* nw    = (const float*)d_in[1];
    const float* nb    = (const float*)d_in[2];
    const float* qkvw  = (const float*)d_in[3];
    const float* outw  = (const float*)d_in[4];
    const float* c1w   = (const float*)d_in[5];
    const float* c1b   = (const float*)d_in[6];
    const float* c2w   = (const float*)d_in[7];
    const float* c2b   = (const float*)d_in[8];
    const float* gamma = (const float*)d_in[9];
    float* out = (float*)d_out;

    int smem_bytes = (64 * XROW * 2 + 320 * WROW * 2) * 2 + (512 + 64 + 64 + 64) * 4;
    cudaFuncSetAttribute(pre_kernel, cudaFuncAttributeMaxDynamicSharedMemorySize,
                         smem_bytes);

    wprep_kernel<<<320, 256>>>(qkvw, c1w, nw, nb);
    pre_kernel<<<128, 256, smem_bytes>>>(x, c1b, c2w, c2b);
    attn_kernel<<<dim3(N_PIX / 64, B_DIM * NH, SPLIT), 128>>>();
    out_kernel<<<dim3((B_DIM * N_PIX) / 64, C_DIM / 64), 256>>>(outw, x, gamma, out);
}

// round 14
// speedup vs baseline: 1.0803x; 1.0448x over previous
#include <cuda_runtime.h>
#include <cuda_bf16.h>
#include <cuda_fp16.h>

#define C_DIM 256
#define N_PIX 4096
#define B_DIM 2
#define RED 64
#define NH 4
#define HD 16
#define SPLIT 4
#define KEYS_PER_SPLIT (N_PIX / SPLIT)   // 1024
#define QSCALE_LOG2E 0.36067376022224085f

// ---------------- scratch (static device globals) ----------------------------
__device__ float g_dyn[B_DIM * N_PIX];
// partials: [s][b][n][r] with r = h*16+d  (contiguous 64-float row per query)
__device__ float g_pacc[SPLIT * B_DIM * N_PIX * RED];
__device__ float g_pl[SPLIT * B_DIM * NH * N_PIX];
__device__ __nv_bfloat16 g_qh[B_DIM * NH * N_PIX * HD];   // [bh][n][d], pre-scaled
__device__ __nv_bfloat16 g_kh[B_DIM * NH * N_PIX * HD];   // [bh][n][d]
__device__ __half        g_vth[B_DIM * NH * HD * N_PIX];  // [bh][d][n], f16
// precomputed weights: rows 0-191 = qkv_w * nw (hi/lo), rows 192-319 = conv1_w
__device__ __nv_bfloat16 g_wh[320 * C_DIM];
__device__ __nv_bfloat16 g_wl[320 * C_DIM];
__device__ float g_W1[192];
__device__ float g_WB[192];
// out_w bf16 hi/lo: [C][RED]
__device__ __nv_bfloat16 g_owh[C_DIM * RED];
__device__ __nv_bfloat16 g_owl[C_DIM * RED];

// ---------------- helpers -----------------------------------------------------
__device__ __forceinline__ unsigned pkhf(float hi, float lo) {
    unsigned d;
    asm("cvt.rn.f16x2.f32 %0, %1, %2;" : "=r"(d) : "f"(hi), "f"(lo));
    return d;
}
__device__ __forceinline__ unsigned hmin2(unsigned a, unsigned b) {
    unsigned d;
    asm("min.f16x2 %0, %1, %2;" : "=r"(d) : "r"(a), "r"(b));
    return d;
}
__device__ __forceinline__ unsigned hex2(unsigned a) {
    unsigned d;
    asm("ex2.approx.f16x2 %0, %1;" : "=r"(d) : "r"(a));
    return d;
}
__device__ __forceinline__ unsigned hadd2u(unsigned a, unsigned b) {
    unsigned d;
    asm("add.f16x2 %0, %1, %2;" : "=r"(d) : "r"(a), "r"(b));
    return d;
}
__device__ __forceinline__ void mma16816(float* d, const unsigned* a,
                                         unsigned b0, unsigned b1) {
    asm volatile(
        "mma.sync.aligned.m16n8k16.row.col.f32.bf16.bf16.f32 "
        "{%0,%1,%2,%3}, {%4,%5,%6,%7}, {%8,%9}, {%0,%1,%2,%3};"
        : "+f"(d[0]), "+f"(d[1]), "+f"(d[2]), "+f"(d[3])
        : "r"(a[0]), "r"(a[1]), "r"(a[2]), "r"(a[3]), "r"(b0), "r"(b1));
}
__device__ __forceinline__ void mma16816h(float* d, const unsigned* a,
                                          unsigned b0, unsigned b1) {
    asm volatile(
        "mma.sync.aligned.m16n8k16.row.col.f32.f16.f16.f32 "
        "{%0,%1,%2,%3}, {%4,%5,%6,%7}, {%8,%9}, {%0,%1,%2,%3};"
        : "+f"(d[0]), "+f"(d[1]), "+f"(d[2]), "+f"(d[3])
        : "r"(a[0]), "r"(a[1]), "r"(a[2]), "r"(a[3]), "r"(b0), "r"(b1));
}

// ---------------- 0) weight prep ---------------------------------------------
// blocks 0..319: qkv/conv1 weights; blocks 320..575: out_w bf16 hi/lo
__global__ void wprep_kernel(const float* __restrict__ qkvw,
                             const float* __restrict__ c1w,
                             const float* __restrict__ outw,
                             const float* __restrict__ nw,
                             const float* __restrict__ nb) {
    int o = blockIdx.x;          // 0..575
    int c = threadIdx.x;         // 0..255
    if (o >= 320) {
        if (c < RED) {
            float w = outw[(o - 320) * RED + c];
            __nv_bfloat16 hi = __float2bfloat16(w);
            g_owh[(o - 320) * RED + c] = hi;
            g_owl[(o - 320) * RED + c] = __float2bfloat16(w - __bfloat162float(hi));
        }
        return;
    }
    __shared__ float r1[8], r2[8];
    float s1 = 0.f, s2 = 0.f;
    if (o < 192) {
        float w = qkvw[o * C_DIM + c];
        float wp = w * nw[c];
        __nv_bfloat16 hi = __float2bfloat16(wp);
        g_wh[o * C_DIM + c] = hi;
        g_wl[o * C_DIM + c] = __float2bfloat16(wp - __bfloat162float(hi));
        s1 = wp;
        s2 = w * nb[c];
    } else {
        float w = c1w[(o - 192) * C_DIM + c];
        __nv_bfloat16 hi = __float2bfloat16(w);
        g_wh[o * C_DIM + c] = hi;
        g_wl[o * C_DIM + c] = __float2bfloat16(w - __bfloat162float(hi));
    }
    if (o < 192) {
#pragma unroll
        for (int m = 16; m; m >>= 1) {
            s1 += __shfl_xor_sync(0xffffffffu, s1, m);
            s2 += __shfl_xor_sync(0xffffffffu, s2, m);
        }
        int wp_ = c >> 5;
        if ((c & 31) == 0) { r1[wp_] = s1; r2[wp_] = s2; }
        __syncthreads();
        if (c == 0) {
            float a = 0.f, bsum = 0.f;
#pragma unroll
            for (int i = 0; i < 8; i++) { a += r1[i]; bsum += r2[i]; }
            g_W1[o] = a;
            g_WB[o] = bsum;
        }
    }
}

// ---------------- 1) fused pre kernel: LN + QKV + dyn via MMA ----------------
#define XROW 264
#define WROW 72

__global__ __launch_bounds__(256, 1) void pre_kernel(const float* __restrict__ x,
                                                     const float* __restrict__ b1,
                                                     const float* __restrict__ w2,
                                                     const float* __restrict__ b2) {
    extern __shared__ __align__(16) char smem[];
    __nv_bfloat16* XH = (__nv_bfloat16*)smem;                  // [64][XROW]
    __nv_bfloat16* XL = XH + 64 * XROW;
    __nv_bfloat16* WHs = XL + 64 * XROW;                       // [320][WROW]
    __nv_bfloat16* WLs = WHs + 320 * WROW;
    float* PS = (float*)(WLs + 320 * WROW);                    // [8][64]
    float* MU = PS + 512;
    float* RS = MU + 64;
    float* DR = RS + 64;

    int t = threadIdx.x;
    int gp0 = blockIdx.x * 64;
    int b = gp0 >> 12, n0 = gp0 & 4095;

    {
        int px = t & 63, grp = t >> 6;
        const float* xb = x + (size_t)(b * C_DIM) * N_PIX + n0 + px;
        float sum = 0.f, sq = 0.f;
#pragma unroll
        for (int i = 0; i < 64; i++) {
            int c = i * 4 + grp;
            float v = xb[(size_t)c * N_PIX];
            sum += v;
            sq += v * v;
            __nv_bfloat16 hi = __float2bfloat16(v);
            XH[px * XROW + c] = hi;
            XL[px * XROW + c] = __float2bfloat16(v - __bfloat162float(hi));
        }
        PS[grp * 64 + px] = sum;
        PS[256 + grp * 64 + px] = sq;
        if (t < 64) DR[t] = 0.f;
    }
    __syncthreads();
    if (t < 64) {
        float a = PS[t] + PS[64 + t] + PS[128 + t] + PS[192 + t];
        float q = PS[256 + t] + PS[320 + t] + PS[384 + t] + PS[448 + t];
        float m = a * (1.f / 256.f);
        float var = q * (1.f / 256.f) - m * m;
        MU[t] = m;
        RS[t] = rsqrtf(var + 1e-5f);
    }

    int warp = t >> 5, lane = t & 31;
    int g = lane >> 2, tg = lane & 3;
    int mg = warp & 3, ng = warp >> 2;
    int px0 = ng * 32;

    float acc[5][4][4];
#pragma unroll
    for (int mi = 0; mi < 5; mi++)
#pragma unroll
        for (int nt = 0; nt < 4; nt++)
#pragma unroll
            for (int f = 0; f < 4; f++) acc[mi][nt][f] = 0.f;

    for (int kc = 0; kc < C_DIM; kc += 64) {
        __syncthreads();
#pragma unroll
        for (int r = 0; r < 10; r++) {
            int e = t + 256 * r;
            int o = e >> 3, kk = e & 7;
            *(uint4*)&WHs[o * WROW + kk * 8] = *(const uint4*)&g_wh[o * C_DIM + kc + kk * 8];
            *(uint4*)&WLs[o * WROW + kk * 8] = *(const uint4*)&g_wl[o * C_DIM + kc + kk * 8];
        }
        __syncthreads();
#pragma unroll
        for (int ks = 0; ks < 4; ks++) {
            int kl = ks * 16 + 2 * tg;
            unsigned bh0[4], bh1[4], bl0[4], bl1[4];
#pragma unroll
            for (int nt = 0; nt < 4; nt++) {
                int xr = (px0 + nt * 8 + g) * XROW + kc + kl;
                bh0[nt] = *(const unsigned*)&XH[xr];
                bh1[nt] = *(const unsigned*)&XH[xr + 8];
                bl0[nt] = *(const unsigned*)&XL[xr];
                bl1[nt] = *(const unsigned*)&XL[xr + 8];
            }
#pragma unroll
            for (int mi = 0; mi < 5; mi++) {
                int o0 = (mg * 5 + mi) * 16;
                unsigned ah[4], al[4];
                ah[0] = *(const unsigned*)&WHs[(o0 + g) * WROW + kl];
                ah[1] = *(const unsigned*)&WHs[(o0 + g + 8) * WROW + kl];
                ah[2] = *(const unsigned*)&WHs[(o0 + g) * WROW + kl + 8];
                ah[3] = *(const unsigned*)&WHs[(o0 + g + 8) * WROW + kl + 8];
                al[0] = *(const unsigned*)&WLs[(o0 + g) * WROW + kl];
                al[1] = *(const unsigned*)&WLs[(o0 + g + 8) * WROW + kl];
                al[2] = *(const unsigned*)&WLs[(o0 + g) * WROW + kl + 8];
                al[3] = *(const unsigned*)&WLs[(o0 + g + 8) * WROW + kl + 8];
#pragma unroll
                for (int nt = 0; nt < 4; nt++) {
                    mma16816(acc[mi][nt], ah, bh0[nt], bh1[nt]);
                    mma16816(acc[mi][nt], ah, bl0[nt], bl1[nt]);
                    mma16816(acc[mi][nt], al, bh0[nt], bh1[nt]);
                }
            }
        }
    }

    // ---- epilogue ----
#pragma unroll
    for (int mi = 0; mi < 5; mi++) {
        int m = mg * 5 + mi;
        if (m >= 12) continue;
#pragma unroll
        for (int nt = 0; nt < 4; nt++) {
            int pxa = px0 + nt * 8 + 2 * tg;
#pragma unroll
            for (int rr = 0; rr < 2; rr++) {
                int o = m * 16 + g + rr * 8;
                float W1v = g_W1[o], WBv = g_WB[o];
                float v0 = RS[pxa] * (acc[mi][nt][rr * 2] - MU[pxa] * W1v) + WBv;
                float v1 = RS[pxa + 1] * (acc[mi][nt][rr * 2 + 1] - MU[pxa + 1] * W1v) + WBv;
                int n = n0 + pxa;
                if (o < 64) {
                    int h = o >> 4, d = o & 15;
                    size_t idx = ((size_t)(b * NH + h) * N_PIX + n) * HD + d;
                    g_qh[idx] = __float2bfloat16(v0 * QSCALE_LOG2E);
                    g_qh[idx + HD] = __float2bfloat16(v1 * QSCALE_LOG2E);
                } else if (o < 128) {
                    int oo = o - 64, h = oo >> 4, d = oo & 15;
                    size_t idx = ((size_t)(b * NH + h) * N_PIX + n) * HD + d;
                    g_kh[idx] = __float2bfloat16(v0);
                    g_kh[idx + HD] = __float2bfloat16(v1);
                } else {
                    int oo = o - 128, h = oo >> 4, d = oo & 15;
                    size_t idx = (size_t)(b * NH + h) * HD * N_PIX + (size_t)d * N_PIX + n;
                    *(unsigned*)&g_vth[idx] = pkhf(v1, v0);
                }
            }
        }
    }
    // --- dyn reduction (conv tiles live in warps mg>=2, m>=12) ---
    if (mg >= 2) {
#pragma unroll
        for (int nt = 0; nt < 4; nt++) {
            float d0 = 0.f, d1 = 0.f;
#pragma unroll
            for (int mi = 0; mi < 5; mi++) {
                int m = mg * 5 + mi;
                if (m < 12) continue;
#pragma unroll
                for (int rr = 0; rr < 2; rr++) {
                    int co = (m - 12) * 16 + g + rr * 8;
                    float bb = b1[co], ww = w2[co];
                    d0 += ww * fmaxf(acc[mi][nt][rr * 2] + bb, 0.f);
                    d1 += ww * fmaxf(acc[mi][nt][rr * 2 + 1] + bb, 0.f);
                }
            }
#pragma unroll
            for (int mk = 4; mk <= 16; mk <<= 1) {
                d0 += __shfl_xor_sync(0xffffffffu, d0, mk);
                d1 += __shfl_xor_sync(0xffffffffu, d1, mk);
            }
            if (g == 0) {
                int pxa = px0 + nt * 8 + 2 * tg;
                atomicAdd(&DR[pxa], d0);
                atomicAdd(&DR[pxa + 1], d1);
            }
        }
    }
    __syncthreads();
    if (t < 64) g_dyn[gp0 + t] = DR[t] + b2[0];
}

// ---------------- 2) tensor-core flash attention (f16x2 softmax) -------------
#define KS_STRIDE 24
#define VT_STRIDE 136
#define S_CLAMP2 0x4B004B00u   // f16x2 {14.0, 14.0}: exp2 overflow guard

__global__ void attn_kernel() {
    __shared__ __align__(16) __nv_bfloat16 Kh_s[128 * KS_STRIDE];
    __shared__ __align__(16) __half Vh_s[HD * VT_STRIDE];

    int tid = threadIdx.x;
    int warp = tid >> 5, lane = tid & 31;
    int g = lane >> 2, tg = lane & 3;
    int bh = blockIdx.y;
    int split = blockIdx.z;
    int qbase = blockIdx.x * 64 + warp * 16;

    const __nv_bfloat16* qb = g_qh + ((size_t)bh * N_PIX + qbase) * HD;
    unsigned aqh[4];
    aqh[0] = *(const unsigned*)(qb + g * HD + 2 * tg);
    aqh[1] = *(const unsigned*)(qb + (g + 8) * HD + 2 * tg);
    aqh[2] = *(const unsigned*)(qb + g * HD + 2 * tg + 8);
    aqh[3] = *(const unsigned*)(qb + (g + 8) * HD + 2 * tg + 8);

    float o0[4] = {0.f, 0.f, 0.f, 0.f};
    float o1[4] = {0.f, 0.f, 0.f, 0.f};
    float l_r = 0.f, l_r8 = 0.f;

    int kstart = split * KEYS_PER_SPLIT;
    const __nv_bfloat16* kh_g = g_kh + (size_t)bh * N_PIX * HD;
    const __half* vh_g = g_vth + (size_t)bh * HD * N_PIX;

    for (int st = 0; st < KEYS_PER_SPLIT / 128; st++) {
        int k0 = kstart + st * 128;
        __syncthreads();
        {
            int key = tid >> 1, seg = tid & 1;
#pragma unroll
            for (int r = 0; r < 2; r++) {
                *(uint4*)&Kh_s[(key + 64 * r) * KS_STRIDE + seg * 8] =
                    *(const uint4*)(kh_g + ((size_t)(k0 + key + 64 * r)) * HD + seg * 8);
            }
            int d = tid >> 4, s8 = tid & 15;
#pragma unroll
            for (int r = 0; r < 2; r++) {
                *(uint4*)&Vh_s[(d + 8 * r) * VT_STRIDE + s8 * 8] =
                    *(const uint4*)(vh_g + (size_t)(d + 8 * r) * N_PIX + k0 + s8 * 8);
            }
        }
        __syncthreads();

#pragma unroll
        for (int c16 = 0; c16 < 128; c16 += 16) {
            float s0[4] = {0.f, 0.f, 0.f, 0.f};
            float s1[4] = {0.f, 0.f, 0.f, 0.f};
            {
                int kb = (c16 + g) * KS_STRIDE + 2 * tg;
                mma16816(s0, aqh, *(const unsigned*)&Kh_s[kb],
                                  *(const unsigned*)&Kh_s[kb + 8]);
            }
            {
                int kb = (c16 + 8 + g) * KS_STRIDE + 2 * tg;
                mma16816(s1, aqh, *(const unsigned*)&Kh_s[kb],
                                  *(const unsigned*)&Kh_s[kb + 8]);
            }
            unsigned pa[4];
            pa[0] = hex2(hmin2(pkhf(s0[1], s0[0]), S_CLAMP2));
            pa[1] = hex2(hmin2(pkhf(s0[3], s0[2]), S_CLAMP2));
            pa[2] = hex2(hmin2(pkhf(s1[1], s1[0]), S_CLAMP2));
            pa[3] = hex2(hmin2(pkhf(s1[3], s1[2]), S_CLAMP2));
            {
                unsigned u0 = hadd2u(pa[0], pa[2]);
                unsigned u1 = hadd2u(pa[1], pa[3]);
                float2 f0 = __half22float2(*(const __half2*)&u0);
                float2 f1 = __half22float2(*(const __half2*)&u1);
                l_r  += f0.x + f0.y;
                l_r8 += f1.x + f1.y;
            }
            {
                int vb = g * VT_STRIDE + c16 + 2 * tg;
                mma16816h(o0, pa, *(const unsigned*)&Vh_s[vb],
                                  *(const unsigned*)&Vh_s[vb + 8]);
            }
            {
                int vb = (8 + g) * VT_STRIDE + c16 + 2 * tg;
                mma16816h(o1, pa, *(const unsigned*)&Vh_s[vb],
                                  *(const unsigned*)&Vh_s[vb + 8]);
            }
        }
    }
    l_r  += __shfl_xor_sync(0xffffffffu, l_r, 1);
    l_r  += __shfl_xor_sync(0xffffffffu, l_r, 2);
    l_r8 += __shfl_xor_sync(0xffffffffu, l_r8, 1);
    l_r8 += __shfl_xor_sync(0xffffffffu, l_r8, 2);

    // partials layout: [s][b][n][r], r = h*16 + d  -> coalesced combine reads
    int h = bh & 3, bb = bh >> 2;
    int row0 = qbase + g, row8 = qbase + g + 8;
    size_t base0 = ((size_t)(split * B_DIM + bb) * N_PIX + row0) * RED + h * HD;
    size_t base8 = ((size_t)(split * B_DIM + bb) * N_PIX + row8) * RED + h * HD;
    *(float2*)(g_pacc + base0 + 2 * tg)     = make_float2(o0[0], o0[1]);
    *(float2*)(g_pacc + base0 + 8 + 2 * tg) = make_float2(o1[0], o1[1]);
    *(float2*)(g_pacc + base8 + 2 * tg)     = make_float2(o0[2], o0[3]);
    *(float2*)(g_pacc + base8 + 8 + 2 * tg) = make_float2(o1[2], o1[3]);
    size_t pb = (size_t)(split * B_DIM * NH + bh) * N_PIX;
    if (tg == 0) {
        g_pl[pb + row0] = l_r;
        g_pl[pb + row8] = l_r8;
    }
}

// ---------------- 3) out projection via MMA (fused combine) + sigmoid --------
// grid (128, 4): x = 64-pixel tile, y = 64-channel chunk.
// M = 64 c (4 m-tiles), N = 64 px (8 n-tiles over 2 warp-groups), K = 64.
// hi/lo bf16 split on BOTH operands (3 MMAs). Ys smem transpose (aliased over
// Ao tiles) keeps the sigmoid epilogue float4-coalesced in NCHW.
#define OROW 72
#define OW_OFF  0                            // WhS [64][OROW] bf16
#define OWL_OFF (64 * OROW * 2)              // WlS
#define AOH_OFF (2 * 64 * OROW * 2)          // AoH [64px][OROW]
#define AOL_OFF (3 * 64 * OROW * 2)          // AoL
#define LI_OFF  (4 * 64 * OROW * 2)          // float[256]
#define OSMEM_TOTAL (LI_OFF + 256 * 4)

__global__ __launch_bounds__(256) void out_kernel(const float* __restrict__ x,
                                                  const float* __restrict__ gamma,
                                                  float* __restrict__ out) {
    __shared__ __align__(16) char smem[OSMEM_TOTAL];
    __nv_bfloat16* WhS = (__nv_bfloat16*)(smem + OW_OFF);
    __nv_bfloat16* WlS = (__nv_bfloat16*)(smem + OWL_OFF);
    __nv_bfloat16* AoH = (__nv_bfloat16*)(smem + AOH_OFF);
    __nv_bfloat16* AoL = (__nv_bfloat16*)(smem + AOL_OFF);
    float* LI = (float*)(smem + LI_OFF);
    float* Ys = (float*)(smem + AOH_OFF);   // [64c][68px] aliases AoH+AoL after MMA

    int tid = threadIdx.x;           // 256
    int warp = tid >> 5, lane = tid & 31;
    int g = lane >> 2, tg = lane & 3;
    int mg = warp & 3, ng = warp >> 2;
    int n0 = blockIdx.x * 64;
    int c0 = blockIdx.y * 64;
    int b = n0 >> 12, nb0 = n0 & 4095;

    // LI: thread -> px = tid>>2, h = tid&3
    {
        int px = tid >> 2, hh = tid & 3;
        int n = nb0 + px;
        int bh = b * NH + hh;
        float l = 0.f;
#pragma unroll
        for (int s = 0; s < SPLIT; s++)
            l += g_pl[((size_t)s * B_DIM * NH + bh) * N_PIX + n];
        LI[px * 4 + hh] = g_dyn[b * N_PIX + n] / l;
    }
    // stage W chunk (bf16 hi/lo), 64 rows x 64 k = 512 uint4, 2 per thread
#pragma unroll
    for (int it = 0; it < 2; it++) {
        int e = tid + 256 * it;
        int row = e >> 3, seg = e & 7;
        *(uint4*)&WhS[row * OROW + seg * 8] = *(const uint4*)&g_owh[(c0 + row) * RED + seg * 8];
        *(uint4*)&WlS[row * OROW + seg * 8] = *(const uint4*)&g_owl[(c0 + row) * RED + seg * 8];
    }
    __syncthreads();
    // stage Ao (combine SPLIT partials * LI -> bf16 hi/lo), coalesced rows
#pragma unroll
    for (int it = 0; it < 16; it++) {
        int e = tid + 256 * it;
        int r = e & 63, px = e >> 6;
        int n = nb0 + px;
        size_t base = ((size_t)b * N_PIX + n) * RED + r;
        float a = 0.f;
#pragma unroll
        for (int s = 0; s < SPLIT; s++)
            a += g_pacc[(size_t)s * (B_DIM * N_PIX * RED) + base];
        a *= LI[px * 4 + (r >> 4)];
        __nv_bfloat16 hi = __float2bfloat16(a);
        AoH[px * OROW + r] = hi;
        AoL[px * OROW + r] = __float2bfloat16(a - __bfloat162float(hi));
    }
    __syncthreads();

    // MMA: warp -> m-tile mg (16 c), n-tiles ng*32 .. +31 (4 of 8 px)
    float acc[4][4];
#pragma unroll
    for (int nt = 0; nt < 4; nt++)
#pragma unroll
        for (int f = 0; f < 4; f++) acc[nt][f] = 0.f;
    int px0 = ng * 32;
#pragma unroll
    for (int ks = 0; ks < 4; ks++) {
        int kl = ks * 16 + 2 * tg;
        unsigned ah[4], al[4];
        ah[0] = *(const unsigned*)&WhS[(mg * 16 + g) * OROW + kl];
        ah[1] = *(const unsigned*)&WhS[(mg * 16 + g + 8) * OROW + kl];
        ah[2] = *(const unsigned*)&WhS[(mg * 16 + g) * OROW + kl + 8];
        ah[3] = *(const unsigned*)&WhS[(mg * 16 + g + 8) * OROW + kl + 8];
        al[0] = *(const unsigned*)&WlS[(mg * 16 + g) * OROW + kl];
        al[1] = *(const unsigned*)&WlS[(mg * 16 + g + 8) * OROW + kl];
        al[2] = *(const unsigned*)&WlS[(mg * 16 + g) * OROW + kl + 8];
        al[3] = *(const unsigned*)&WlS[(mg * 16 + g + 8) * OROW + kl + 8];
#pragma unroll
        for (int nt = 0; nt < 4; nt++) {
            int br = (px0 + nt * 8 + g) * OROW + kl;
            unsigned bh0 = *(const unsigned*)&AoH[br];
            unsigned bh1 = *(const unsigned*)&AoH[br + 8];
            unsigned bl0 = *(const unsigned*)&AoL[br];
            unsigned bl1 = *(const unsigned*)&AoL[br + 8];
            mma16816(acc[nt], ah, bh0, bh1);
            mma16816(acc[nt], ah, bl0, bl1);
            mma16816(acc[nt], al, bh0, bh1);
        }
    }
    __syncthreads();   // all MMA reads of AoH/AoL done before Ys aliases them
    // scatter accs to Ys[c][px]
#pragma unroll
    for (int nt = 0; nt < 4; nt++) {
        int px = px0 + nt * 8 + 2 * tg;
        *(float2*)&Ys[(mg * 16 + g) * 68 + px]     = make_float2(acc[nt][0], acc[nt][1]);
        *(float2*)&Ys[(mg * 16 + g + 8) * 68 + px] = make_float2(acc[nt][2], acc[nt][3]);
    }
    __syncthreads();

    // sigmoid epilogue, float4-coalesced NCHW stores
    int tx = tid & 15, ty = tid >> 4;
    float gm = gamma[0];
    int n = nb0 + ty * 4;
#pragma unroll
    for (int j = 0; j < 4; j++) {
        int cl = tx * 4 + j;
        float4 y4 = *(const float4*)&Ys[cl * 68 + ty * 4];
        size_t base = ((size_t)(b * C_DIM + c0 + cl)) * N_PIX + n;
        float4 xv = *(const float4*)(x + base);
        float4 r;
        r.x = 1.f / (1.f + __expf(-(gm * y4.x + xv.x)));
        r.y = 1.f / (1.f + __expf(-(gm * y4.y + xv.y)));
        r.z = 1.f / (1.f + __expf(-(gm * y4.z + xv.z)));
        r.w = 1.f / (1.f + __expf(-(gm * y4.w + xv.w)));
        *(float4*)(out + base) = r;
    }
}

// ---------------- launch ------------------------------------------------------
extern "C" void kernel_launch(void* const* d_in, const int* in_sizes, int n_in,
                              void* d_out, int out_size) {
    const float* x     = (const float*)d_in[0];
    const float* nw    = (const float*)d_in[1];
    const float* nb    = (const float*)d_in[2];
    const float* qkvw  = (const float*)d_in[3];
    const float* outw  = (const float*)d_in[4];
    const float* c1w   = (const float*)d_in[5];
    const float* c1b   = (const float*)d_in[6];
    const float* c2w   = (const float*)d_in[7];
    const float* c2b   = (const float*)d_in[8];
    const float* gamma = (const float*)d_in[9];
    float* out = (float*)d_out;

    int smem_bytes = (64 * XROW * 2 + 320 * WROW * 2) * 2 + (512 + 64 + 64 + 64) * 4;
    cudaFuncSetAttribute(pre_kernel, cudaFuncAttributeMaxDynamicSharedMemorySize,
                         smem_bytes);

    wprep_kernel<<<576, 256>>>(qkvw, c1w, outw, nw, nb);
    pre_kernel<<<128, 256, smem_bytes>>>(x, c1b, c2w, c2b);
    attn_kernel<<<dim3(N_PIX / 64, B_DIM * NH, SPLIT), 128>>>();
    out_kernel<<<dim3((B_DIM * N_PIX) / 64, C_DIM / 64), 256>>>(x, gamma, out);
}

// round 15
// speedup vs baseline: 1.1656x; 1.0790x over previous
#include <cuda_runtime.h>
#include <cuda_bf16.h>
#include <cuda_fp16.h>

#define C_DIM 256
#define N_PIX 4096
#define B_DIM 2
#define RED 64
#define NH 4
#define HD 16
#define SPLIT 4
#define KEYS_PER_SPLIT (N_PIX / SPLIT)   // 1024
#define QSCALE_LOG2E 0.36067376022224085f

// ---------------- scratch (static device globals) ----------------------------
__device__ float g_dyn[B_DIM * N_PIX];
// partials: [s][b][n][r] with r = h*16+d  (contiguous 64-float row per query)
__device__ float g_pacc[SPLIT * B_DIM * N_PIX * RED];
__device__ float g_pl[SPLIT * B_DIM * NH * N_PIX];
__device__ __nv_bfloat16 g_qh[B_DIM * NH * N_PIX * HD];   // [bh][n][d], pre-scaled
__device__ __nv_bfloat16 g_kh[B_DIM * NH * N_PIX * HD];   // [bh][n][d]
__device__ __half        g_vth[B_DIM * NH * HD * N_PIX];  // [bh][d][n], f16
// precomputed weights: rows 0-191 = qkv_w * nw (hi/lo), rows 192-319 = conv1_w
__device__ __nv_bfloat16 g_wh[320 * C_DIM];
__device__ __nv_bfloat16 g_wl[320 * C_DIM];
__device__ float g_W1[192];
__device__ float g_WB[192];
// out_w bf16 hi/lo: [C][RED]
__device__ __nv_bfloat16 g_owh[C_DIM * RED];
__device__ __nv_bfloat16 g_owl[C_DIM * RED];

// ---------------- helpers -----------------------------------------------------
__device__ __forceinline__ unsigned pkhf(float hi, float lo) {
    unsigned d;
    asm("cvt.rn.f16x2.f32 %0, %1, %2;" : "=r"(d) : "f"(hi), "f"(lo));
    return d;
}
__device__ __forceinline__ unsigned pkbf(float hi, float lo) {
    unsigned d;
    asm("cvt.rn.satfinite.bf16x2.f32 %0, %1, %2;" : "=r"(d) : "f"(hi), "f"(lo));
    return d;
}
__device__ __forceinline__ unsigned hex2(unsigned a) {
    unsigned d;
    asm("ex2.approx.f16x2 %0, %1;" : "=r"(d) : "r"(a));
    return d;
}
__device__ __forceinline__ unsigned hadd2u(unsigned a, unsigned b) {
    unsigned d;
    asm("add.f16x2 %0, %1, %2;" : "=r"(d) : "r"(a), "r"(b));
    return d;
}
__device__ __forceinline__ void mma16816(float* d, const unsigned* a,
                                         unsigned b0, unsigned b1) {
    asm volatile(
        "mma.sync.aligned.m16n8k16.row.col.f32.bf16.bf16.f32 "
        "{%0,%1,%2,%3}, {%4,%5,%6,%7}, {%8,%9}, {%0,%1,%2,%3};"
        : "+f"(d[0]), "+f"(d[1]), "+f"(d[2]), "+f"(d[3])
        : "r"(a[0]), "r"(a[1]), "r"(a[2]), "r"(a[3]), "r"(b0), "r"(b1));
}
__device__ __forceinline__ void mma16816h(float* d, const unsigned* a,
                                          unsigned b0, unsigned b1) {
    asm volatile(
        "mma.sync.aligned.m16n8k16.row.col.f32.f16.f16.f32 "
        "{%0,%1,%2,%3}, {%4,%5,%6,%7}, {%8,%9}, {%0,%1,%2,%3};"
        : "+f"(d[0]), "+f"(d[1]), "+f"(d[2]), "+f"(d[3])
        : "r"(a[0]), "r"(a[1]), "r"(a[2]), "r"(a[3]), "r"(b0), "r"(b1));
}

// ---------------- 0) weight prep ---------------------------------------------
// blocks 0..319: qkv/conv1 weights; blocks 320..575: out_w bf16 hi/lo
__global__ void wprep_kernel(const float* __restrict__ qkvw,
                             const float* __restrict__ c1w,
                             const float* __restrict__ outw,
                             const float* __restrict__ nw,
                             const float* __restrict__ nb) {
    int o = blockIdx.x;          // 0..575
    int c = threadIdx.x;         // 0..255
    if (o >= 320) {
        if (c < RED) {
            float w = outw[(o - 320) * RED + c];
            __nv_bfloat16 hi = __float2bfloat16(w);
            g_owh[(o - 320) * RED + c] = hi;
            g_owl[(o - 320) * RED + c] = __float2bfloat16(w - __bfloat162float(hi));
        }
        return;
    }
    __shared__ float r1[8], r2[8];
    float s1 = 0.f, s2 = 0.f;
    if (o < 192) {
        float w = qkvw[o * C_DIM + c];
        float wp = w * nw[c];
        __nv_bfloat16 hi = __float2bfloat16(wp);
        g_wh[o * C_DIM + c] = hi;
        g_wl[o * C_DIM + c] = __float2bfloat16(wp - __bfloat162float(hi));
        s1 = wp;
        s2 = w * nb[c];
    } else {
        float w = c1w[(o - 192) * C_DIM + c];
        __nv_bfloat16 hi = __float2bfloat16(w);
        g_wh[o * C_DIM + c] = hi;
        g_wl[o * C_DIM + c] = __float2bfloat16(w - __bfloat162float(hi));
    }
    if (o < 192) {
#pragma unroll
        for (int m = 16; m; m >>= 1) {
            s1 += __shfl_xor_sync(0xffffffffu, s1, m);
            s2 += __shfl_xor_sync(0xffffffffu, s2, m);
        }
        int wp_ = c >> 5;
        if ((c & 31) == 0) { r1[wp_] = s1; r2[wp_] = s2; }
        __syncthreads();
        if (c == 0) {
            float a = 0.f, bsum = 0.f;
#pragma unroll
            for (int i = 0; i < 8; i++) { a += r1[i]; bsum += r2[i]; }
            g_W1[o] = a;
            g_WB[o] = bsum;
        }
    }
}

// ---------------- 1) fused pre kernel: LN + QKV + dyn via MMA ----------------
#define XROW 264
#define WROW 72

__global__ __launch_bounds__(256, 1) void pre_kernel(const float* __restrict__ x,
                                                     const float* __restrict__ b1,
                                                     const float* __restrict__ w2,
                                                     const float* __restrict__ b2) {
    extern __shared__ __align__(16) char smem[];
    __nv_bfloat16* XH = (__nv_bfloat16*)smem;                  // [64][XROW]
    __nv_bfloat16* XL = XH + 64 * XROW;
    __nv_bfloat16* WHs = XL + 64 * XROW;                       // [320][WROW]
    __nv_bfloat16* WLs = WHs + 320 * WROW;
    float* PS = (float*)(WLs + 320 * WROW);                    // [8][64]
    float* MU = PS + 512;
    float* RS = MU + 64;
    float* DR = RS + 64;

    int t = threadIdx.x;
    int gp0 = blockIdx.x * 64;
    int b = gp0 >> 12, n0 = gp0 & 4095;

    {
        int px = t & 63, grp = t >> 6;
        const float* xb = x + (size_t)(b * C_DIM) * N_PIX + n0 + px;
        float sum = 0.f, sq = 0.f;
#pragma unroll
        for (int i = 0; i < 64; i++) {
            int c = i * 4 + grp;
            float v = xb[(size_t)c * N_PIX];
            sum += v;
            sq += v * v;
            __nv_bfloat16 hi = __float2bfloat16(v);
            XH[px * XROW + c] = hi;
            XL[px * XROW + c] = __float2bfloat16(v - __bfloat162float(hi));
        }
        PS[grp * 64 + px] = sum;
        PS[256 + grp * 64 + px] = sq;
        if (t < 64) DR[t] = 0.f;
    }
    __syncthreads();
    if (t < 64) {
        float a = PS[t] + PS[64 + t] + PS[128 + t] + PS[192 + t];
        float q = PS[256 + t] + PS[320 + t] + PS[384 + t] + PS[448 + t];
        float m = a * (1.f / 256.f);
        float var = q * (1.f / 256.f) - m * m;
        MU[t] = m;
        RS[t] = rsqrtf(var + 1e-5f);
    }

    int warp = t >> 5, lane = t & 31;
    int g = lane >> 2, tg = lane & 3;
    int mg = warp & 3, ng = warp >> 2;
    int px0 = ng * 32;

    float acc[5][4][4];
#pragma unroll
    for (int mi = 0; mi < 5; mi++)
#pragma unroll
        for (int nt = 0; nt < 4; nt++)
#pragma unroll
            for (int f = 0; f < 4; f++) acc[mi][nt][f] = 0.f;

    for (int kc = 0; kc < C_DIM; kc += 64) {
        __syncthreads();
#pragma unroll
        for (int r = 0; r < 10; r++) {
            int e = t + 256 * r;
            int o = e >> 3, kk = e & 7;
            *(uint4*)&WHs[o * WROW + kk * 8] = *(const uint4*)&g_wh[o * C_DIM + kc + kk * 8];
            *(uint4*)&WLs[o * WROW + kk * 8] = *(const uint4*)&g_wl[o * C_DIM + kc + kk * 8];
        }
        __syncthreads();
#pragma unroll
        for (int ks = 0; ks < 4; ks++) {
            int kl = ks * 16 + 2 * tg;
            unsigned bh0[4], bh1[4], bl0[4], bl1[4];
#pragma unroll
            for (int nt = 0; nt < 4; nt++) {
                int xr = (px0 + nt * 8 + g) * XROW + kc + kl;
                bh0[nt] = *(const unsigned*)&XH[xr];
                bh1[nt] = *(const unsigned*)&XH[xr + 8];
                bl0[nt] = *(const unsigned*)&XL[xr];
                bl1[nt] = *(const unsigned*)&XL[xr + 8];
            }
#pragma unroll
            for (int mi = 0; mi < 5; mi++) {
                int o0 = (mg * 5 + mi) * 16;
                unsigned ah[4], al[4];
                ah[0] = *(const unsigned*)&WHs[(o0 + g) * WROW + kl];
                ah[1] = *(const unsigned*)&WHs[(o0 + g + 8) * WROW + kl];
                ah[2] = *(const unsigned*)&WHs[(o0 + g) * WROW + kl + 8];
                ah[3] = *(const unsigned*)&WHs[(o0 + g + 8) * WROW + kl + 8];
                al[0] = *(const unsigned*)&WLs[(o0 + g) * WROW + kl];
                al[1] = *(const unsigned*)&WLs[(o0 + g + 8) * WROW + kl];
                al[2] = *(const unsigned*)&WLs[(o0 + g) * WROW + kl + 8];
                al[3] = *(const unsigned*)&WLs[(o0 + g + 8) * WROW + kl + 8];
#pragma unroll
                for (int nt = 0; nt < 4; nt++) {
                    mma16816(acc[mi][nt], ah, bh0[nt], bh1[nt]);
                    mma16816(acc[mi][nt], ah, bl0[nt], bl1[nt]);
                    mma16816(acc[mi][nt], al, bh0[nt], bh1[nt]);
                }
            }
        }
    }

    // ---- epilogue ----
#pragma unroll
    for (int mi = 0; mi < 5; mi++) {
        int m = mg * 5 + mi;
        if (m >= 12) continue;
#pragma unroll
        for (int nt = 0; nt < 4; nt++) {
            int pxa = px0 + nt * 8 + 2 * tg;
#pragma unroll
            for (int rr = 0; rr < 2; rr++) {
                int o = m * 16 + g + rr * 8;
                float W1v = g_W1[o], WBv = g_WB[o];
                float v0 = RS[pxa] * (acc[mi][nt][rr * 2] - MU[pxa] * W1v) + WBv;
                float v1 = RS[pxa + 1] * (acc[mi][nt][rr * 2 + 1] - MU[pxa + 1] * W1v) + WBv;
                int n = n0 + pxa;
                if (o < 64) {
                    int h = o >> 4, d = o & 15;
                    size_t idx = ((size_t)(b * NH + h) * N_PIX + n) * HD + d;
                    g_qh[idx] = __float2bfloat16(v0 * QSCALE_LOG2E);
                    g_qh[idx + HD] = __float2bfloat16(v1 * QSCALE_LOG2E);
                } else if (o < 128) {
                    int oo = o - 64, h = oo >> 4, d = oo & 15;
                    size_t idx = ((size_t)(b * NH + h) * N_PIX + n) * HD + d;
                    g_kh[idx] = __float2bfloat16(v0);
                    g_kh[idx + HD] = __float2bfloat16(v1);
                } else {
                    int oo = o - 128, h = oo >> 4, d = oo & 15;
                    size_t idx = (size_t)(b * NH + h) * HD * N_PIX + (size_t)d * N_PIX + n;
                    *(unsigned*)&g_vth[idx] = pkhf(v1, v0);
                }
            }
        }
    }
    // --- dyn reduction (conv tiles live in warps mg>=2, m>=12) ---
    if (mg >= 2) {
#pragma unroll
        for (int nt = 0; nt < 4; nt++) {
            float d0 = 0.f, d1 = 0.f;
#pragma unroll
            for (int mi = 0; mi < 5; mi++) {
                int m = mg * 5 + mi;
                if (m < 12) continue;
#pragma unroll
                for (int rr = 0; rr < 2; rr++) {
                    int co = (m - 12) * 16 + g + rr * 8;
                    float bb = b1[co], ww = w2[co];
                    d0 += ww * fmaxf(acc[mi][nt][rr * 2] + bb, 0.f);
                    d1 += ww * fmaxf(acc[mi][nt][rr * 2 + 1] + bb, 0.f);
                }
            }
#pragma unroll
            for (int mk = 4; mk <= 16; mk <<= 1) {
                d0 += __shfl_xor_sync(0xffffffffu, d0, mk);
                d1 += __shfl_xor_sync(0xffffffffu, d1, mk);
            }
            if (g == 0) {
                int pxa = px0 + nt * 8 + 2 * tg;
                atomicAdd(&DR[pxa], d0);
                atomicAdd(&DR[pxa + 1], d1);
            }
        }
    }
    __syncthreads();
    if (t < 64) g_dyn[gp0 + t] = DR[t] + b2[0];
}

// ---------------- 2) tensor-core flash attention (f16x2 softmax) -------------
// No clamp: |s| <= ~9 stat bound vs f16 ex2 overflow at 15.98 (2^7 headroom).
#define KS_STRIDE 24
#define VT_STRIDE 136

__global__ void attn_kernel() {
    __shared__ __align__(16) __nv_bfloat16 Kh_s[128 * KS_STRIDE];
    __shared__ __align__(16) __half Vh_s[HD * VT_STRIDE];

    int tid = threadIdx.x;
    int warp = tid >> 5, lane = tid & 31;
    int g = lane >> 2, tg = lane & 3;
    int bh = blockIdx.y;
    int split = blockIdx.z;
    int qbase = blockIdx.x * 64 + warp * 16;

    const __nv_bfloat16* qb = g_qh + ((size_t)bh * N_PIX + qbase) * HD;
    unsigned aqh[4];
    aqh[0] = *(const unsigned*)(qb + g * HD + 2 * tg);
    aqh[1] = *(const unsigned*)(qb + (g + 8) * HD + 2 * tg);
    aqh[2] = *(const unsigned*)(qb + g * HD + 2 * tg + 8);
    aqh[3] = *(const unsigned*)(qb + (g + 8) * HD + 2 * tg + 8);

    float o0[4] = {0.f, 0.f, 0.f, 0.f};
    float o1[4] = {0.f, 0.f, 0.f, 0.f};
    float l_r = 0.f, l_r8 = 0.f;

    int kstart = split * KEYS_PER_SPLIT;
    const __nv_bfloat16* kh_g = g_kh + (size_t)bh * N_PIX * HD;
    const __half* vh_g = g_vth + (size_t)bh * HD * N_PIX;

    for (int st = 0; st < KEYS_PER_SPLIT / 128; st++) {
        int k0 = kstart + st * 128;
        __syncthreads();
        {
            int key = tid >> 1, seg = tid & 1;
#pragma unroll
            for (int r = 0; r < 2; r++) {
                *(uint4*)&Kh_s[(key + 64 * r) * KS_STRIDE + seg * 8] =
                    *(const uint4*)(kh_g + ((size_t)(k0 + key + 64 * r)) * HD + seg * 8);
            }
            int d = tid >> 4, s8 = tid & 15;
#pragma unroll
            for (int r = 0; r < 2; r++) {
                *(uint4*)&Vh_s[(d + 8 * r) * VT_STRIDE + s8 * 8] =
                    *(const uint4*)(vh_g + (size_t)(d + 8 * r) * N_PIX + k0 + s8 * 8);
            }
        }
        __syncthreads();

#pragma unroll
        for (int c16 = 0; c16 < 128; c16 += 16) {
            float s0[4] = {0.f, 0.f, 0.f, 0.f};
            float s1[4] = {0.f, 0.f, 0.f, 0.f};
            {
                int kb = (c16 + g) * KS_STRIDE + 2 * tg;
                mma16816(s0, aqh, *(const unsigned*)&Kh_s[kb],
                                  *(const unsigned*)&Kh_s[kb + 8]);
            }
            {
                int kb = (c16 + 8 + g) * KS_STRIDE + 2 * tg;
                mma16816(s1, aqh, *(const unsigned*)&Kh_s[kb],
                                  *(const unsigned*)&Kh_s[kb + 8]);
            }
            unsigned pa[4];
            pa[0] = hex2(pkhf(s0[1], s0[0]));
            pa[1] = hex2(pkhf(s0[3], s0[2]));
            pa[2] = hex2(pkhf(s1[1], s1[0]));
            pa[3] = hex2(pkhf(s1[3], s1[2]));
            {
                unsigned u0 = hadd2u(pa[0], pa[2]);
                unsigned u1 = hadd2u(pa[1], pa[3]);
                float2 f0 = __half22float2(*(const __half2*)&u0);
                float2 f1 = __half22float2(*(const __half2*)&u1);
                l_r  += f0.x + f0.y;
                l_r8 += f1.x + f1.y;
            }
            {
                int vb = g * VT_STRIDE + c16 + 2 * tg;
                mma16816h(o0, pa, *(const unsigned*)&Vh_s[vb],
                                  *(const unsigned*)&Vh_s[vb + 8]);
            }
            {
                int vb = (8 + g) * VT_STRIDE + c16 + 2 * tg;
                mma16816h(o1, pa, *(const unsigned*)&Vh_s[vb],
                                  *(const unsigned*)&Vh_s[vb + 8]);
            }
        }
    }
    l_r  += __shfl_xor_sync(0xffffffffu, l_r, 1);
    l_r  += __shfl_xor_sync(0xffffffffu, l_r, 2);
    l_r8 += __shfl_xor_sync(0xffffffffu, l_r8, 1);
    l_r8 += __shfl_xor_sync(0xffffffffu, l_r8, 2);

    // partials layout: [s][b][n][r], r = h*16 + d  -> coalesced combine reads
    int h = bh & 3, bb = bh >> 2;
    int row0 = qbase + g, row8 = qbase + g + 8;
    size_t base0 = ((size_t)(split * B_DIM + bb) * N_PIX + row0) * RED + h * HD;
    size_t base8 = ((size_t)(split * B_DIM + bb) * N_PIX + row8) * RED + h * HD;
    *(float2*)(g_pacc + base0 + 2 * tg)     = make_float2(o0[0], o0[1]);
    *(float2*)(g_pacc + base0 + 8 + 2 * tg) = make_float2(o1[0], o1[1]);
    *(float2*)(g_pacc + base8 + 2 * tg)     = make_float2(o0[2], o0[3]);
    *(float2*)(g_pacc + base8 + 8 + 2 * tg) = make_float2(o1[2], o1[3]);
    size_t pb = (size_t)(split * B_DIM * NH + bh) * N_PIX;
    if (tg == 0) {
        g_pl[pb + row0] = l_r;
        g_pl[pb + row8] = l_r8;
    }
}

// ---------------- 3) out projection via MMA (fused combine) + sigmoid --------
// grid (256, 2): x = 32-pixel tile, y = 128-channel chunk -> 512 blocks.
// M = 128 c (8 m-tiles, one per warp), N = 32 px (4 n-tiles), K = 64.
// Float4 combine staging (high MLP); hi/lo bf16 split (3 MMAs).
// Ys transpose aliases the W tiles for coalesced NCHW sigmoid stores.
#define OROW 72
__global__ __launch_bounds__(256) void out_kernel(const float* __restrict__ x,
                                                  const float* __restrict__ gamma,
                                                  float* __restrict__ out) {
    __shared__ __align__(16) __nv_bfloat16 WhS[128 * OROW];
    __shared__ __align__(16) __nv_bfloat16 WlS[128 * OROW];
    __shared__ __align__(16) __nv_bfloat16 AoH[32 * OROW];
    __shared__ __align__(16) __nv_bfloat16 AoL[32 * OROW];
    __shared__ float LI[32][4];
    float* Ys = (float*)WhS;          // [128c][36px] (18.4KB) aliases W tiles

    int tid = threadIdx.x;            // 256
    int warp = tid >> 5, lane = tid & 31;
    int g = lane >> 2, tg = lane & 3;
    int n0 = blockIdx.x * 32;
    int c0 = blockIdx.y * 128;
    int b = n0 >> 12, nb0 = n0 & 4095;

    // LI: threads 0..127 -> px = tid>>2, h = tid&3
    if (tid < 128) {
        int px = tid >> 2, hh = tid & 3;
        int n = nb0 + px;
        int bh = b * NH + hh;
        float l = 0.f;
#pragma unroll
        for (int s = 0; s < SPLIT; s++)
            l += g_pl[((size_t)s * B_DIM * NH + bh) * N_PIX + n];
        LI[px][hh] = g_dyn[b * N_PIX + n] / l;
    }
    // stage W chunk (bf16 hi/lo): 128 rows x 64 k = 1024 uint4 each, 4/thread
#pragma unroll
    for (int it = 0; it < 4; it++) {
        int e = tid + 256 * it;
        int row = e >> 3, seg = e & 7;
        *(uint4*)&WhS[row * OROW + seg * 8] = *(const uint4*)&g_owh[(c0 + row) * RED + seg * 8];
        *(uint4*)&WlS[row * OROW + seg * 8] = *(const uint4*)&g_owl[(c0 + row) * RED + seg * 8];
    }
    __syncthreads();
    // stage Ao: float4 combine over SPLIT, * LI, -> bf16 hi/lo
#pragma unroll
    for (int it = 0; it < 2; it++) {
        int e = tid + 256 * it;          // 0..511
        int px = e >> 4, r4 = e & 15;    // r0 = r4*4 (within one head)
        int r0 = r4 * 4;
        int n = nb0 + px;
        size_t base = (((size_t)b * N_PIX + n) * RED + r0) >> 2;  // float4 idx
        float4 a = make_float4(0.f, 0.f, 0.f, 0.f);
#pragma unroll
        for (int s = 0; s < SPLIT; s++) {
            float4 t4 = ((const float4*)g_pacc)[(size_t)s * (B_DIM * N_PIX * RED / 4) + base];
            a.x += t4.x; a.y += t4.y; a.z += t4.z; a.w += t4.w;
        }
        float sc = LI[px][r0 >> 4];
        a.x *= sc; a.y *= sc; a.z *= sc; a.w *= sc;
        unsigned h01 = pkbf(a.y, a.x);
        unsigned h23 = pkbf(a.w, a.z);
        float lx0 = a.x - __uint_as_float(h01 << 16);
        float lx1 = a.y - __uint_as_float(h01 & 0xffff0000u);
        float lx2 = a.z - __uint_as_float(h23 << 16);
        float lx3 = a.w - __uint_as_float(h23 & 0xffff0000u);
        *(unsigned*)&AoH[px * OROW + r0]     = h01;
        *(unsigned*)&AoH[px * OROW + r0 + 2] = h23;
        *(unsigned*)&AoL[px * OROW + r0]     = pkbf(lx1, lx0);
        *(unsigned*)&AoL[px * OROW + r0 + 2] = pkbf(lx3, lx2);
    }
    __syncthreads();

    // MMA: warp = m-tile (16 c), 4 n-tiles x 4 k-steps x 3 MMAs
    float acc[4][4];
#pragma unroll
    for (int nt = 0; nt < 4; nt++)
#pragma unroll
        for (int f = 0; f < 4; f++) acc[nt][f] = 0.f;
#pragma unroll
    for (int ks = 0; ks < 4; ks++) {
        int kl = ks * 16 + 2 * tg;
        unsigned ah[4], al[4];
        ah[0] = *(const unsigned*)&WhS[(warp * 16 + g) * OROW + kl];
        ah[1] = *(const unsigned*)&WhS[(warp * 16 + g + 8) * OROW + kl];
        ah[2] = *(const unsigned*)&WhS[(warp * 16 + g) * OROW + kl + 8];
        ah[3] = *(const unsigned*)&WhS[(warp * 16 + g + 8) * OROW + kl + 8];
        al[0] = *(const unsigned*)&WlS[(warp * 16 + g) * OROW + kl];
        al[1] = *(const unsigned*)&WlS[(warp * 16 + g + 8) * OROW + kl];
        al[2] = *(const unsigned*)&WlS[(warp * 16 + g) * OROW + kl + 8];
        al[3] = *(const unsigned*)&WlS[(warp * 16 + g + 8) * OROW + kl + 8];
#pragma unroll
        for (int nt = 0; nt < 4; nt++) {
            int br = (nt * 8 + g) * OROW + kl;
            unsigned bh0 = *(const unsigned*)&AoH[br];
            unsigned bh1 = *(const unsigned*)&AoH[br + 8];
            unsigned bl0 = *(const unsigned*)&AoL[br];
            unsigned bl1 = *(const unsigned*)&AoL[br + 8];
            mma16816(acc[nt], ah, bh0, bh1);
            mma16816(acc[nt], ah, bl0, bl1);
            mma16816(acc[nt], al, bh0, bh1);
        }
    }
    __syncthreads();   // W reads done before Ys aliases them
    // scatter accs to Ys[c][px] (row = 36 floats = 144B, 16-aligned)
#pragma unroll
    for (int nt = 0; nt < 4; nt++) {
        int px = nt * 8 + 2 * tg;
        *(float2*)&Ys[(warp * 16 + g) * 36 + px]     = make_float2(acc[nt][0], acc[nt][1]);
        *(float2*)&Ys[(warp * 16 + g + 8) * 36 + px] = make_float2(acc[nt][2], acc[nt][3]);
    }
    __syncthreads();

    // sigmoid epilogue: 128 c x 32 px; 8 lanes sweep px -> 128B coalesced
    float gm = gamma[0];
    int px4 = tid & 7;                // float4 group within 32 px
    int cb = tid >> 3;                // 0..31
#pragma unroll
    for (int j = 0; j < 4; j++) {
        int c = cb + 32 * j;
        float4 y4 = *(const float4*)&Ys[c * 36 + px4 * 4];
        size_t base = ((size_t)(b * C_DIM + c0 + c)) * N_PIX + nb0 + px4 * 4;
        float4 xv = *(const float4*)(x + base);
        float4 r;
        r.x = 1.f / (1.f + __expf(-(gm * y4.x + xv.x)));
        r.y = 1.f / (1.f + __expf(-(gm * y4.y + xv.y)));
        r.z = 1.f / (1.f + __expf(-(gm * y4.z + xv.z)));
        r.w = 1.f / (1.f + __expf(-(gm * y4.w + xv.w)));
        *(float4*)(out + base) = r;
    }
}

// ---------------- launch ------------------------------------------------------
extern "C" void kernel_launch(void* const* d_in, const int* in_sizes, int n_in,
                              void* d_out, int out_size) {
    const float* x     = (const float*)d_in[0];
    const float* nw    = (const float*)d_in[1];
    const float* nb    = (const float*)d_in[2];
    const float* qkvw  = (const float*)d_in[3];
    const float* outw  = (const float*)d_in[4];
    const float* c1w   = (const float*)d_in[5];
    const float* c1b   = (const float*)d_in[6];
    const float* c2w   = (const float*)d_in[7];
    const float* c2b   = (const float*)d_in[8];
    const float* gamma = (const float*)d_in[9];
    float* out = (float*)d_out;

    int smem_bytes = (64 * XROW * 2 + 320 * WROW * 2) * 2 + (512 + 64 + 64 + 64) * 4;
    cudaFuncSetAttribute(pre_kernel, cudaFuncAttributeMaxDynamicSharedMemorySize,
                         smem_bytes);

    wprep_kernel<<<576, 256>>>(qkvw, c1w, outw, nw, nb);
    pre_kernel<<<128, 256, smem_bytes>>>(x, c1b, c2w, c2b);
    attn_kernel<<<dim3(N_PIX / 64, B_DIM * NH, SPLIT), 128>>>();
    out_kernel<<<dim3((B_DIM * N_PIX) / 32, C_DIM / 128), 256>>>(x, gamma, out);
}